// round 2
// baseline (speedup 1.0000x reference)
#include <cuda_runtime.h>

// ---------------------------------------------------------------------------
// SpatialRangeAttention — GB300 sm_103a
// Inputs (metadata order):
//  0 spatial_feats [2,64,112,112] f32
//  1 semantic_feats[2,64,112,112] f32
//  2..7   rp_w1[64,64], rp_b1[64], rp_g[64], rp_beta[64], rp_w2[64,64], rp_b2[64]
//  8..13  fx_w1[49,113], fx_b1[49], fx_g[49], fx_beta[49], fx_w2[49,49], fx_b2[49]
//  14..19 op_w1[64,64], op_b1[64], op_g[64], op_beta[64], op_w2[64,64], op_b2[64]
//  20 sigma_spatial scalar
// Output: [2,64,112,112] f32
// ---------------------------------------------------------------------------

#define BB   2
#define CC   64
#define HH   112
#define WW   112
#define HWP  (HH*WW)      // 12544
#define NPIX (BB*HWP)     // 25088
#define N2   49

// Scratch (pixel-major layouts)
__device__ float g_sem_t[NPIX*CC];   // semantic transposed [pix][c]
__device__ float g_spa_t[NPIX*CC];   // spatial  transposed [pix][c]
__device__ float g_px[NPIX*CC];      // range-projected features [pix][c]
__device__ float g_comb[NPIX*N2];    // bilateral / final weights [pix][n]

// ---------------------------------------------------------------------------
// K0: transpose both inputs [B,C,HW] -> [B*HW, C]
// ---------------------------------------------------------------------------
__global__ __launch_bounds__(256) void k_transpose2(
    const float* __restrict__ sem, const float* __restrict__ spa)
{
    __shared__ float t1[32][33];
    __shared__ float t2[32][33];
    int b  = blockIdx.z;
    int c0 = blockIdx.y * 32;
    int p0 = blockIdx.x * 32;
    int tx = threadIdx.x, ty = threadIdx.y;
    #pragma unroll
    for (int i = ty; i < 32; i += 8) {
        int c = c0 + i, p = p0 + tx;
        t1[i][tx] = sem[(b*CC + c)*HWP + p];
        t2[i][tx] = spa[(b*CC + c)*HWP + p];
    }
    __syncthreads();
    #pragma unroll
    for (int i = ty; i < 32; i += 8) {
        int p = p0 + i, c = c0 + tx;
        g_sem_t[(b*HWP + p)*CC + c] = t1[tx][i];
        g_spa_t[(b*HWP + p)*CC + c] = t2[tx][i];
    }
}

// ---------------------------------------------------------------------------
// K1: range_proj: px = conv1x1(W2) . silu(LN(conv1x1(W1) . sem))
// warp-per-4-pixels, weights transposed in smem ([c][o] so lane reads are
// conflict-free), x broadcast from smem tile.
// ---------------------------------------------------------------------------
__global__ __launch_bounds__(256) void k_range(
    const float* __restrict__ w1, const float* __restrict__ b1,
    const float* __restrict__ g,  const float* __restrict__ be,
    const float* __restrict__ w2, const float* __restrict__ b2)
{
    __shared__ float W1s[4096], W2s[4096];
    __shared__ float b1s[64], gs[64], bes[64], b2s[64];
    __shared__ float xs[32*64];
    int tid = threadIdx.x, lane = tid & 31, w = tid >> 5;

    for (int i = tid; i < 4096; i += 256) {
        int o = i >> 6, c = i & 63;
        W1s[c*64 + o] = w1[i];
        W2s[c*64 + o] = w2[i];
    }
    if (tid < 64) { b1s[tid]=b1[tid]; gs[tid]=g[tid]; bes[tid]=be[tid]; b2s[tid]=b2[tid]; }

    int p0 = blockIdx.x * 32;
    for (int i = tid; i < 32*64; i += 256) xs[i] = g_sem_t[p0*CC + i];
    __syncthreads();

    int q0 = w * 4;
    float y[4][2];
    #pragma unroll
    for (int q = 0; q < 4; q++) { y[q][0] = b1s[lane]; y[q][1] = b1s[lane+32]; }

    for (int c = 0; c < 64; c++) {
        float a0 = W1s[c*64 + lane], a1 = W1s[c*64 + lane + 32];
        #pragma unroll
        for (int q = 0; q < 4; q++) {
            float xv = xs[(q0+q)*64 + c];
            y[q][0] += a0 * xv; y[q][1] += a1 * xv;
        }
    }
    // LN + SiLU per pixel, write hidden back into xs
    #pragma unroll
    for (int q = 0; q < 4; q++) {
        float s = y[q][0] + y[q][1];
        #pragma unroll
        for (int o = 16; o; o >>= 1) s += __shfl_xor_sync(0xffffffffu, s, o);
        float mean = s * (1.f/64.f);
        float d0 = y[q][0] - mean, d1 = y[q][1] - mean;
        float v = d0*d0 + d1*d1;
        #pragma unroll
        for (int o = 16; o; o >>= 1) v += __shfl_xor_sync(0xffffffffu, v, o);
        float rstd = rsqrtf(v * (1.f/64.f) + 1e-6f);
        float h0 = gs[lane]    * d0 * rstd + bes[lane];
        float h1 = gs[lane+32] * d1 * rstd + bes[lane+32];
        h0 = h0 / (1.f + __expf(-h0));
        h1 = h1 / (1.f + __expf(-h1));
        xs[(q0+q)*64 + lane]      = h0;
        xs[(q0+q)*64 + lane + 32] = h1;
    }
    __syncwarp();

    #pragma unroll
    for (int q = 0; q < 4; q++) { y[q][0] = b2s[lane]; y[q][1] = b2s[lane+32]; }
    for (int c = 0; c < 64; c++) {
        float a0 = W2s[c*64 + lane], a1 = W2s[c*64 + lane + 32];
        #pragma unroll
        for (int q = 0; q < 4; q++) {
            float xv = xs[(q0+q)*64 + c];
            y[q][0] += a0 * xv; y[q][1] += a1 * xv;
        }
    }
    #pragma unroll
    for (int q = 0; q < 4; q++) {
        int p = p0 + q0 + q;
        g_px[p*CC + lane]      = y[q][0];
        g_px[p*CC + lane + 32] = y[q][1];
    }
}

// ---------------------------------------------------------------------------
// K2: bilateral combined kernel: comb0[n] = exp(-||px_nbr-px||^2/(2C)) * sw[n]
// (0 when neighbor out of bounds). warp-per-pixel.
// ---------------------------------------------------------------------------
__global__ __launch_bounds__(256) void k_bilateral(const float* __restrict__ sigma)
{
    __shared__ float sw_s[N2];
    int tid = threadIdx.x, lane = tid & 31, w = tid >> 5;
    if (tid < N2) {
        float sg = *sigma;
        int dy = tid / 7 - 3, dx = tid % 7 - 3;
        float d2 = (float)(dy*dy + dx*dx);
        sw_s[tid] = __expf(-d2 / (2.f * sg * sg));
    }
    __syncthreads();

    int p = blockIdx.x * 8 + w;
    int b = p / HWP, pp = p % HWP, yy = pp / WW, xx = pp % WW;

    float c0 = g_px[p*CC + lane], c1 = g_px[p*CC + lane + 32];

    for (int n = 0; n < N2; n++) {
        int dy = n / 7 - 3, dx = n % 7 - 3;
        int ny = yy + dy, nx = xx + dx;
        float outv = 0.f;
        if (ny >= 0 && ny < HH && nx >= 0 && nx < WW) {
            const float* q = &g_px[(b*HWP + ny*WW + nx)*CC];
            float d0 = q[lane]    - c0;
            float d1 = q[lane+32] - c1;
            float s = d0*d0 + d1*d1;
            #pragma unroll
            for (int o = 16; o; o >>= 1) s += __shfl_xor_sync(0xffffffffu, s, o);
            outv = __expf(-s * (1.f/128.f)) * sw_s[n];   // 2*C = 128
        }
        if (lane == 0) g_comb[p*N2 + n] = outv;
    }
}

// ---------------------------------------------------------------------------
// K3a: fixup: f = conv49x113 -> LN(49) -> SiLU -> conv49x49; gate + normalize
// Weights zero-padded to 64 output lanes -> branch-free lanes.
// ---------------------------------------------------------------------------
__global__ __launch_bounds__(256) void k_fixup(
    const float* __restrict__ w1, const float* __restrict__ b1,
    const float* __restrict__ g,  const float* __restrict__ be,
    const float* __restrict__ w2, const float* __restrict__ b2)
{
    __shared__ float W1p[113*64];   // [j][o], o padded to 64
    __shared__ float W2p[49*64];
    __shared__ float b1p[64], gp[64], bep[64], b2p[64];
    __shared__ float ins[8][113];
    int tid = threadIdx.x, lane = tid & 31, w = tid >> 5;

    for (int i = tid; i < 113*64; i += 256) {
        int j = i >> 6, o = i & 63;
        W1p[i] = (o < 49) ? w1[o*113 + j] : 0.f;
    }
    for (int i = tid; i < 49*64; i += 256) {
        int j = i >> 6, o = i & 63;
        W2p[i] = (o < 49) ? w2[o*49 + j] : 0.f;
    }
    if (tid < 64) {
        b1p[tid] = (tid < 49) ? b1[tid] : 0.f;
        gp[tid]  = (tid < 49) ? g[tid]  : 0.f;
        bep[tid] = (tid < 49) ? be[tid] : 0.f;
        b2p[tid] = (tid < 49) ? b2[tid] : 0.f;
    }
    __syncthreads();

    const bool has2 = (lane + 32) < N2;  // lane < 17

    for (int it = 0; it < 4; it++) {
        int p = blockIdx.x*32 + w*4 + it;
        for (int j = lane; j < 113; j += 32)
            ins[w][j] = (j < N2) ? g_comb[p*N2 + j] : g_sem_t[p*CC + (j - N2)];
        __syncwarp();

        float cb0 = ins[w][lane];
        float cb1 = has2 ? ins[w][lane + 32] : 0.f;

        float y0 = b1p[lane], y1 = b1p[lane + 32];
        for (int j = 0; j < 113; j++) {
            float xv = ins[w][j];
            y0 += W1p[j*64 + lane]      * xv;
            y1 += W1p[j*64 + lane + 32] * xv;
        }
        // LN over 49 channels
        float s = y0 + (has2 ? y1 : 0.f);
        #pragma unroll
        for (int o = 16; o; o >>= 1) s += __shfl_xor_sync(0xffffffffu, s, o);
        float mean = s * (1.f/49.f);
        float d0 = y0 - mean, d1 = y1 - mean;
        float v = d0*d0 + (has2 ? d1*d1 : 0.f);
        #pragma unroll
        for (int o = 16; o; o >>= 1) v += __shfl_xor_sync(0xffffffffu, v, o);
        float rstd = rsqrtf(v * (1.f/49.f) + 1e-6f);
        float h0 = gp[lane]      * d0 * rstd + bep[lane];
        float h1 = gp[lane + 32] * d1 * rstd + bep[lane + 32];
        h0 = h0 / (1.f + __expf(-h0));
        h1 = h1 / (1.f + __expf(-h1));
        __syncwarp();
        ins[w][lane] = h0;
        if (has2) ins[w][lane + 32] = h1;
        __syncwarp();

        y0 = b2p[lane]; y1 = b2p[lane + 32];
        for (int j = 0; j < 49; j++) {
            float xv = ins[w][j];
            y0 += W2p[j*64 + lane]      * xv;
            y1 += W2p[j*64 + lane + 32] * xv;
        }
        float wv0 = cb0 * (1.f + 1.f/(1.f + __expf(-y0)));
        float wv1 = cb1 * (1.f + 1.f/(1.f + __expf(-y1)));
        float ss = wv0 + wv1;
        #pragma unroll
        for (int o = 16; o; o >>= 1) ss += __shfl_xor_sync(0xffffffffu, ss, o);
        float inv = 1.f / (ss + 1e-7f);
        g_comb[p*N2 + lane] = wv0 * inv;
        if (has2) g_comb[p*N2 + lane + 32] = wv1 * inv;
        __syncwarp();
    }
}

// ---------------------------------------------------------------------------
// K3b: weighted neighborhood reduction + output_proj (conv -> LN -> conv)
// ---------------------------------------------------------------------------
__global__ __launch_bounds__(256) void k_output(
    const float* __restrict__ w1, const float* __restrict__ b1,
    const float* __restrict__ g,  const float* __restrict__ be,
    const float* __restrict__ w2, const float* __restrict__ b2,
    float* __restrict__ out)
{
    __shared__ float W1s[4096], W2s[4096];
    __shared__ float b1s[64], gs[64], bes[64], b2s[64];
    __shared__ float wsb[8][56];
    __shared__ float os[8][64];
    int tid = threadIdx.x, lane = tid & 31, w = tid >> 5;

    for (int i = tid; i < 4096; i += 256) {
        int o = i >> 6, c = i & 63;
        W1s[c*64 + o] = w1[i];
        W2s[c*64 + o] = w2[i];
    }
    if (tid < 64) { b1s[tid]=b1[tid]; gs[tid]=g[tid]; bes[tid]=be[tid]; b2s[tid]=b2[tid]; }
    __syncthreads();

    for (int it = 0; it < 4; it++) {
        int p = blockIdx.x*32 + w*4 + it;
        int b = p / HWP, pp = p % HWP, yy = pp / WW, xx = pp % WW;

        for (int n = lane; n < N2; n += 32) wsb[w][n] = g_comb[p*N2 + n];
        __syncwarp();

        float a0 = 0.f, a1 = 0.f;
        for (int n = 0; n < N2; n++) {
            int dy = n / 7 - 3, dx = n % 7 - 3;
            int ny = yy + dy, nx = xx + dx;
            if (ny >= 0 && ny < HH && nx >= 0 && nx < WW) {
                float wv = wsb[w][n];
                const float* sp = &g_spa_t[(b*HWP + ny*WW + nx)*CC];
                a0 += sp[lane]      * wv;
                a1 += sp[lane + 32] * wv;
            }
        }
        __syncwarp();
        os[w][lane] = a0; os[w][lane + 32] = a1;
        __syncwarp();

        float y0 = b1s[lane], y1 = b1s[lane + 32];
        for (int c = 0; c < 64; c++) {
            float xv = os[w][c];
            y0 += W1s[c*64 + lane]      * xv;
            y1 += W1s[c*64 + lane + 32] * xv;
        }
        float s = y0 + y1;
        #pragma unroll
        for (int o = 16; o; o >>= 1) s += __shfl_xor_sync(0xffffffffu, s, o);
        float mean = s * (1.f/64.f);
        float d0 = y0 - mean, d1 = y1 - mean;
        float v = d0*d0 + d1*d1;
        #pragma unroll
        for (int o = 16; o; o >>= 1) v += __shfl_xor_sync(0xffffffffu, v, o);
        float rstd = rsqrtf(v * (1.f/64.f) + 1e-6f);
        float t0 = gs[lane]      * d0 * rstd + bes[lane];
        float t1 = gs[lane + 32] * d1 * rstd + bes[lane + 32];
        __syncwarp();
        os[w][lane] = t0; os[w][lane + 32] = t1;
        __syncwarp();

        y0 = b2s[lane]; y1 = b2s[lane + 32];
        for (int c = 0; c < 64; c++) {
            float xv = os[w][c];
            y0 += W2s[c*64 + lane]      * xv;
            y1 += W2s[c*64 + lane + 32] * xv;
        }
        out[(b*CC + lane)*HWP + pp]      = y0;
        out[(b*CC + lane + 32)*HWP + pp] = y1;
        __syncwarp();
    }
}

// ---------------------------------------------------------------------------
extern "C" void kernel_launch(void* const* d_in, const int* in_sizes, int n_in,
                              void* d_out, int out_size)
{
    const float* spa = (const float*)d_in[0];
    const float* sem = (const float*)d_in[1];

    dim3 tg(HWP/32, CC/32, BB), tb(32, 8);
    k_transpose2<<<tg, tb>>>(sem, spa);

    k_range<<<NPIX/32, 256>>>((const float*)d_in[2], (const float*)d_in[3],
                              (const float*)d_in[4], (const float*)d_in[5],
                              (const float*)d_in[6], (const float*)d_in[7]);

    k_bilateral<<<NPIX/8, 256>>>((const float*)d_in[20]);

    k_fixup<<<NPIX/32, 256>>>((const float*)d_in[8],  (const float*)d_in[9],
                              (const float*)d_in[10], (const float*)d_in[11],
                              (const float*)d_in[12], (const float*)d_in[13]);

    k_output<<<NPIX/32, 256>>>((const float*)d_in[14], (const float*)d_in[15],
                               (const float*)d_in[16], (const float*)d_in[17],
                               (const float*)d_in[18], (const float*)d_in[19],
                               (float*)d_out);
}

// round 3
// speedup vs baseline: 1.0050x; 1.0050x over previous
#include <cuda_runtime.h>

// ---------------------------------------------------------------------------
// SpatialRangeAttention — GB300 sm_103a
// Inputs (metadata order):
//  0 spatial_feats [2,64,112,112] f32
//  1 semantic_feats[2,64,112,112] f32
//  2..7   rp_w1[64,64], rp_b1[64], rp_g[64], rp_beta[64], rp_w2[64,64], rp_b2[64]
//  8..13  fx_w1[49,113], fx_b1[49], fx_g[49], fx_beta[49], fx_w2[49,49], fx_b2[49]
//  14..19 op_w1[64,64], op_b1[64], op_g[64], op_beta[64], op_w2[64,64], op_b2[64]
//  20 sigma_spatial scalar
// Output: [2,64,112,112] f32
// ---------------------------------------------------------------------------

#define BB   2
#define CC   64
#define HH   112
#define WW   112
#define HWP  (HH*WW)      // 12544
#define NPIX (BB*HWP)     // 25088
#define N2   49

// Scratch (pixel-major layouts)
__device__ float g_sem_t[NPIX*CC];   // semantic transposed [pix][c]
__device__ float g_spa_t[NPIX*CC];   // spatial  transposed [pix][c]
__device__ float g_px[NPIX*CC];      // range-projected features [pix][c]
__device__ float g_comb[NPIX*N2];    // bilateral / final weights [pix][n]

// ---------------------------------------------------------------------------
// K0: transpose both inputs [B,C,HW] -> [B*HW, C]
// ---------------------------------------------------------------------------
__global__ __launch_bounds__(256) void k_transpose2(
    const float* __restrict__ sem, const float* __restrict__ spa)
{
    __shared__ float t1[32][33];
    __shared__ float t2[32][33];
    int b  = blockIdx.z;
    int c0 = blockIdx.y * 32;
    int p0 = blockIdx.x * 32;
    int tx = threadIdx.x, ty = threadIdx.y;
    #pragma unroll
    for (int i = ty; i < 32; i += 8) {
        int c = c0 + i, p = p0 + tx;
        t1[i][tx] = sem[(b*CC + c)*HWP + p];
        t2[i][tx] = spa[(b*CC + c)*HWP + p];
    }
    __syncthreads();
    #pragma unroll
    for (int i = ty; i < 32; i += 8) {
        int p = p0 + i, c = c0 + tx;
        g_sem_t[(b*HWP + p)*CC + c] = t1[tx][i];
        g_spa_t[(b*HWP + p)*CC + c] = t2[tx][i];
    }
}

// ---------------------------------------------------------------------------
// K1: range_proj: px = conv1x1(W2) . silu(LN(conv1x1(W1) . sem))
// warp-per-4-pixels, weights transposed in smem ([c][o] so lane reads are
// conflict-free), x broadcast from smem tile.
// ---------------------------------------------------------------------------
__global__ __launch_bounds__(256) void k_range(
    const float* __restrict__ w1, const float* __restrict__ b1,
    const float* __restrict__ g,  const float* __restrict__ be,
    const float* __restrict__ w2, const float* __restrict__ b2)
{
    __shared__ float W1s[4096], W2s[4096];
    __shared__ float b1s[64], gs[64], bes[64], b2s[64];
    __shared__ float xs[32*64];
    int tid = threadIdx.x, lane = tid & 31, w = tid >> 5;

    for (int i = tid; i < 4096; i += 256) {
        int o = i >> 6, c = i & 63;
        W1s[c*64 + o] = w1[i];
        W2s[c*64 + o] = w2[i];
    }
    if (tid < 64) { b1s[tid]=b1[tid]; gs[tid]=g[tid]; bes[tid]=be[tid]; b2s[tid]=b2[tid]; }

    int p0 = blockIdx.x * 32;
    for (int i = tid; i < 32*64; i += 256) xs[i] = g_sem_t[p0*CC + i];
    __syncthreads();

    int q0 = w * 4;
    float y[4][2];
    #pragma unroll
    for (int q = 0; q < 4; q++) { y[q][0] = b1s[lane]; y[q][1] = b1s[lane+32]; }

    for (int c = 0; c < 64; c++) {
        float a0 = W1s[c*64 + lane], a1 = W1s[c*64 + lane + 32];
        #pragma unroll
        for (int q = 0; q < 4; q++) {
            float xv = xs[(q0+q)*64 + c];
            y[q][0] += a0 * xv; y[q][1] += a1 * xv;
        }
    }
    // LN + SiLU per pixel, write hidden back into xs
    #pragma unroll
    for (int q = 0; q < 4; q++) {
        float s = y[q][0] + y[q][1];
        #pragma unroll
        for (int o = 16; o; o >>= 1) s += __shfl_xor_sync(0xffffffffu, s, o);
        float mean = s * (1.f/64.f);
        float d0 = y[q][0] - mean, d1 = y[q][1] - mean;
        float v = d0*d0 + d1*d1;
        #pragma unroll
        for (int o = 16; o; o >>= 1) v += __shfl_xor_sync(0xffffffffu, v, o);
        float rstd = rsqrtf(v * (1.f/64.f) + 1e-6f);
        float h0 = gs[lane]    * d0 * rstd + bes[lane];
        float h1 = gs[lane+32] * d1 * rstd + bes[lane+32];
        h0 = h0 / (1.f + __expf(-h0));
        h1 = h1 / (1.f + __expf(-h1));
        xs[(q0+q)*64 + lane]      = h0;
        xs[(q0+q)*64 + lane + 32] = h1;
    }
    __syncwarp();

    #pragma unroll
    for (int q = 0; q < 4; q++) { y[q][0] = b2s[lane]; y[q][1] = b2s[lane+32]; }
    for (int c = 0; c < 64; c++) {
        float a0 = W2s[c*64 + lane], a1 = W2s[c*64 + lane + 32];
        #pragma unroll
        for (int q = 0; q < 4; q++) {
            float xv = xs[(q0+q)*64 + c];
            y[q][0] += a0 * xv; y[q][1] += a1 * xv;
        }
    }
    #pragma unroll
    for (int q = 0; q < 4; q++) {
        int p = p0 + q0 + q;
        g_px[p*CC + lane]      = y[q][0];
        g_px[p*CC + lane + 32] = y[q][1];
    }
}

// ---------------------------------------------------------------------------
// K2: bilateral combined kernel: comb0[n] = exp(-||px_nbr-px||^2/(2C)) * sw[n]
// (0 when neighbor out of bounds). warp-per-pixel.
// ---------------------------------------------------------------------------
__global__ __launch_bounds__(256) void k_bilateral(const float* __restrict__ sigma)
{
    __shared__ float sw_s[N2];
    int tid = threadIdx.x, lane = tid & 31, w = tid >> 5;
    if (tid < N2) {
        float sg = *sigma;
        int dy = tid / 7 - 3, dx = tid % 7 - 3;
        float d2 = (float)(dy*dy + dx*dx);
        sw_s[tid] = __expf(-d2 / (2.f * sg * sg));
    }
    __syncthreads();

    int p = blockIdx.x * 8 + w;
    int b = p / HWP, pp = p % HWP, yy = pp / WW, xx = pp % WW;

    float c0 = g_px[p*CC + lane], c1 = g_px[p*CC + lane + 32];

    for (int n = 0; n < N2; n++) {
        int dy = n / 7 - 3, dx = n % 7 - 3;
        int ny = yy + dy, nx = xx + dx;
        float outv = 0.f;
        if (ny >= 0 && ny < HH && nx >= 0 && nx < WW) {
            const float* q = &g_px[(b*HWP + ny*WW + nx)*CC];
            float d0 = q[lane]    - c0;
            float d1 = q[lane+32] - c1;
            float s = d0*d0 + d1*d1;
            #pragma unroll
            for (int o = 16; o; o >>= 1) s += __shfl_xor_sync(0xffffffffu, s, o);
            outv = __expf(-s * (1.f/128.f)) * sw_s[n];   // 2*C = 128
        }
        if (lane == 0) g_comb[p*N2 + n] = outv;
    }
}

// ---------------------------------------------------------------------------
// K3a: fixup: f = conv49x113 -> LN(49) -> SiLU -> conv49x49; gate + normalize
// Weights zero-padded to 64 output lanes -> branch-free lanes.
// ---------------------------------------------------------------------------
__global__ __launch_bounds__(256) void k_fixup(
    const float* __restrict__ w1, const float* __restrict__ b1,
    const float* __restrict__ g,  const float* __restrict__ be,
    const float* __restrict__ w2, const float* __restrict__ b2)
{
    __shared__ float W1p[113*64];   // [j][o], o padded to 64
    __shared__ float W2p[49*64];
    __shared__ float b1p[64], gp[64], bep[64], b2p[64];
    __shared__ float ins[8][113];
    int tid = threadIdx.x, lane = tid & 31, w = tid >> 5;

    for (int i = tid; i < 113*64; i += 256) {
        int j = i >> 6, o = i & 63;
        W1p[i] = (o < 49) ? w1[o*113 + j] : 0.f;
    }
    for (int i = tid; i < 49*64; i += 256) {
        int j = i >> 6, o = i & 63;
        W2p[i] = (o < 49) ? w2[o*49 + j] : 0.f;
    }
    if (tid < 64) {
        b1p[tid] = (tid < 49) ? b1[tid] : 0.f;
        gp[tid]  = (tid < 49) ? g[tid]  : 0.f;
        bep[tid] = (tid < 49) ? be[tid] : 0.f;
        b2p[tid] = (tid < 49) ? b2[tid] : 0.f;
    }
    __syncthreads();

    const bool has2 = (lane + 32) < N2;  // lane < 17

    for (int it = 0; it < 4; it++) {
        int p = blockIdx.x*32 + w*4 + it;
        for (int j = lane; j < 113; j += 32)
            ins[w][j] = (j < N2) ? g_comb[p*N2 + j] : g_sem_t[p*CC + (j - N2)];
        __syncwarp();

        float cb0 = ins[w][lane];
        float cb1 = has2 ? ins[w][lane + 32] : 0.f;

        float y0 = b1p[lane], y1 = b1p[lane + 32];
        for (int j = 0; j < 113; j++) {
            float xv = ins[w][j];
            y0 += W1p[j*64 + lane]      * xv;
            y1 += W1p[j*64 + lane + 32] * xv;
        }
        // LN over 49 channels
        float s = y0 + (has2 ? y1 : 0.f);
        #pragma unroll
        for (int o = 16; o; o >>= 1) s += __shfl_xor_sync(0xffffffffu, s, o);
        float mean = s * (1.f/49.f);
        float d0 = y0 - mean, d1 = y1 - mean;
        float v = d0*d0 + (has2 ? d1*d1 : 0.f);
        #pragma unroll
        for (int o = 16; o; o >>= 1) v += __shfl_xor_sync(0xffffffffu, v, o);
        float rstd = rsqrtf(v * (1.f/49.f) + 1e-6f);
        float h0 = gp[lane]      * d0 * rstd + bep[lane];
        float h1 = gp[lane + 32] * d1 * rstd + bep[lane + 32];
        h0 = h0 / (1.f + __expf(-h0));
        h1 = h1 / (1.f + __expf(-h1));
        __syncwarp();
        ins[w][lane] = h0;
        if (has2) ins[w][lane + 32] = h1;
        __syncwarp();

        y0 = b2p[lane]; y1 = b2p[lane + 32];
        for (int j = 0; j < 49; j++) {
            float xv = ins[w][j];
            y0 += W2p[j*64 + lane]      * xv;
            y1 += W2p[j*64 + lane + 32] * xv;
        }
        float wv0 = cb0 * (1.f + 1.f/(1.f + __expf(-y0)));
        float wv1 = cb1 * (1.f + 1.f/(1.f + __expf(-y1)));
        float ss = wv0 + wv1;
        #pragma unroll
        for (int o = 16; o; o >>= 1) ss += __shfl_xor_sync(0xffffffffu, ss, o);
        float inv = 1.f / (ss + 1e-7f);
        g_comb[p*N2 + lane] = wv0 * inv;
        if (has2) g_comb[p*N2 + lane + 32] = wv1 * inv;
        __syncwarp();
    }
}

// ---------------------------------------------------------------------------
// K3b: weighted neighborhood reduction + output_proj (conv -> LN -> conv)
// ---------------------------------------------------------------------------
__global__ __launch_bounds__(256) void k_output(
    const float* __restrict__ w1, const float* __restrict__ b1,
    const float* __restrict__ g,  const float* __restrict__ be,
    const float* __restrict__ w2, const float* __restrict__ b2,
    float* __restrict__ out)
{
    __shared__ float W1s[4096], W2s[4096];
    __shared__ float b1s[64], gs[64], bes[64], b2s[64];
    __shared__ float wsb[8][56];
    __shared__ float os[8][64];
    int tid = threadIdx.x, lane = tid & 31, w = tid >> 5;

    for (int i = tid; i < 4096; i += 256) {
        int o = i >> 6, c = i & 63;
        W1s[c*64 + o] = w1[i];
        W2s[c*64 + o] = w2[i];
    }
    if (tid < 64) { b1s[tid]=b1[tid]; gs[tid]=g[tid]; bes[tid]=be[tid]; b2s[tid]=b2[tid]; }
    __syncthreads();

    for (int it = 0; it < 4; it++) {
        int p = blockIdx.x*32 + w*4 + it;
        int b = p / HWP, pp = p % HWP, yy = pp / WW, xx = pp % WW;

        for (int n = lane; n < N2; n += 32) wsb[w][n] = g_comb[p*N2 + n];
        __syncwarp();

        float a0 = 0.f, a1 = 0.f;
        for (int n = 0; n < N2; n++) {
            int dy = n / 7 - 3, dx = n % 7 - 3;
            int ny = yy + dy, nx = xx + dx;
            if (ny >= 0 && ny < HH && nx >= 0 && nx < WW) {
                float wv = wsb[w][n];
                const float* sp = &g_spa_t[(b*HWP + ny*WW + nx)*CC];
                a0 += sp[lane]      * wv;
                a1 += sp[lane + 32] * wv;
            }
        }
        __syncwarp();
        os[w][lane] = a0; os[w][lane + 32] = a1;
        __syncwarp();

        float y0 = b1s[lane], y1 = b1s[lane + 32];
        for (int c = 0; c < 64; c++) {
            float xv = os[w][c];
            y0 += W1s[c*64 + lane]      * xv;
            y1 += W1s[c*64 + lane + 32] * xv;
        }
        float s = y0 + y1;
        #pragma unroll
        for (int o = 16; o; o >>= 1) s += __shfl_xor_sync(0xffffffffu, s, o);
        float mean = s * (1.f/64.f);
        float d0 = y0 - mean, d1 = y1 - mean;
        float v = d0*d0 + d1*d1;
        #pragma unroll
        for (int o = 16; o; o >>= 1) v += __shfl_xor_sync(0xffffffffu, v, o);
        float rstd = rsqrtf(v * (1.f/64.f) + 1e-6f);
        float t0 = gs[lane]      * d0 * rstd + bes[lane];
        float t1 = gs[lane + 32] * d1 * rstd + bes[lane + 32];
        __syncwarp();
        os[w][lane] = t0; os[w][lane + 32] = t1;
        __syncwarp();

        y0 = b2s[lane]; y1 = b2s[lane + 32];
        for (int c = 0; c < 64; c++) {
            float xv = os[w][c];
            y0 += W2s[c*64 + lane]      * xv;
            y1 += W2s[c*64 + lane + 32] * xv;
        }
        out[(b*CC + lane)*HWP + pp]      = y0;
        out[(b*CC + lane + 32)*HWP + pp] = y1;
        __syncwarp();
    }
}

// ---------------------------------------------------------------------------
extern "C" void kernel_launch(void* const* d_in, const int* in_sizes, int n_in,
                              void* d_out, int out_size)
{
    const float* spa = (const float*)d_in[0];
    const float* sem = (const float*)d_in[1];

    dim3 tg(HWP/32, CC/32, BB), tb(32, 8);
    k_transpose2<<<tg, tb>>>(sem, spa);

    k_range<<<NPIX/32, 256>>>((const float*)d_in[2], (const float*)d_in[3],
                              (const float*)d_in[4], (const float*)d_in[5],
                              (const float*)d_in[6], (const float*)d_in[7]);

    k_bilateral<<<NPIX/8, 256>>>((const float*)d_in[20]);

    k_fixup<<<NPIX/32, 256>>>((const float*)d_in[8],  (const float*)d_in[9],
                              (const float*)d_in[10], (const float*)d_in[11],
                              (const float*)d_in[12], (const float*)d_in[13]);

    k_output<<<NPIX/32, 256>>>((const float*)d_in[14], (const float*)d_in[15],
                               (const float*)d_in[16], (const float*)d_in[17],
                               (const float*)d_in[18], (const float*)d_in[19],
                               (float*)d_out);
}

// round 4
// speedup vs baseline: 1.1362x; 1.1306x over previous
#include <cuda_runtime.h>

// ---------------------------------------------------------------------------
// SpatialRangeAttention — GB300 sm_103a
// Inputs (metadata order):
//  0 spatial_feats [2,64,112,112] f32
//  1 semantic_feats[2,64,112,112] f32
//  2..7   rp_w1[64,64], rp_b1[64], rp_g[64], rp_beta[64], rp_w2[64,64], rp_b2[64]
//  8..13  fx_w1[49,113], fx_b1[49], fx_g[49], fx_beta[49], fx_w2[49,49], fx_b2[49]
//  14..19 op_w1[64,64], op_b1[64], op_g[64], op_beta[64], op_w2[64,64], op_b2[64]
//  20 sigma_spatial scalar
// Output: [2,64,112,112] f32
// ---------------------------------------------------------------------------

#define BB   2
#define CC   64
#define HH   112
#define WW   112
#define HWP  (HH*WW)      // 12544
#define NPIX (BB*HWP)     // 25088
#define N2   49

// Scratch (pixel-major layouts)
__device__ float g_sem_t[NPIX*CC];   // semantic transposed [pix][c]
__device__ float g_spa_t[NPIX*CC];   // spatial  transposed [pix][c]
__device__ float g_px[NPIX*CC];      // range-projected features [pix][c]
__device__ float g_comb[NPIX*N2];    // bilateral / final weights [pix][n]

// ---------------------------------------------------------------------------
// K0: transpose both inputs [B,C,HW] -> [B*HW, C]
// ---------------------------------------------------------------------------
__global__ __launch_bounds__(256) void k_transpose2(
    const float* __restrict__ sem, const float* __restrict__ spa)
{
    __shared__ float t1[32][33];
    __shared__ float t2[32][33];
    int b  = blockIdx.z;
    int c0 = blockIdx.y * 32;
    int p0 = blockIdx.x * 32;
    int tx = threadIdx.x, ty = threadIdx.y;
    #pragma unroll
    for (int i = ty; i < 32; i += 8) {
        int c = c0 + i, p = p0 + tx;
        t1[i][tx] = sem[(b*CC + c)*HWP + p];
        t2[i][tx] = spa[(b*CC + c)*HWP + p];
    }
    __syncthreads();
    #pragma unroll
    for (int i = ty; i < 32; i += 8) {
        int p = p0 + i, c = c0 + tx;
        g_sem_t[(b*HWP + p)*CC + c] = t1[tx][i];
        g_spa_t[(b*HWP + p)*CC + c] = t2[tx][i];
    }
}

// ---------------------------------------------------------------------------
// K1: range_proj: px = conv1x1(W2) . silu(LN(conv1x1(W1) . sem))
// warp handles 4 pixels concurrently; activations staged warp-locally in
// xs[c][4] so one LDS.128 broadcast feeds 8 FMAs; weight LDS amortized 4x.
// ---------------------------------------------------------------------------
__global__ __launch_bounds__(256) void k_range(
    const float* __restrict__ w1, const float* __restrict__ b1,
    const float* __restrict__ g,  const float* __restrict__ be,
    const float* __restrict__ w2, const float* __restrict__ b2)
{
    __shared__ float W1s[4096], W2s[4096];
    __shared__ float b1s[64], gs[64], bes[64], b2s[64];
    __shared__ __align__(16) float xs[8][64][4];
    int tid = threadIdx.x, lane = tid & 31, w = tid >> 5;

    for (int i = tid; i < 4096; i += 256) {
        int o = i >> 6, c = i & 63;
        W1s[c*64 + o] = w1[i];
        W2s[c*64 + o] = w2[i];
    }
    if (tid < 64) { b1s[tid]=b1[tid]; gs[tid]=g[tid]; bes[tid]=be[tid]; b2s[tid]=b2[tid]; }

    int pbase = blockIdx.x * 32 + w * 4;
    // stage 4 pixels' features into [c][q]
    #pragma unroll
    for (int q = 0; q < 4; q++) {
        xs[w][lane][q]      = g_sem_t[(pbase+q)*CC + lane];
        xs[w][lane + 32][q] = g_sem_t[(pbase+q)*CC + lane + 32];
    }
    __syncthreads();   // weights ready (also covers warp-local xs)

    float y0[4], y1[4];
    #pragma unroll
    for (int q = 0; q < 4; q++) { y0[q] = b1s[lane]; y1[q] = b1s[lane+32]; }

    for (int c = 0; c < 64; c++) {
        float a0 = W1s[c*64 + lane], a1 = W1s[c*64 + lane + 32];
        float4 xv = *(const float4*)&xs[w][c][0];
        y0[0] += a0*xv.x; y1[0] += a1*xv.x;
        y0[1] += a0*xv.y; y1[1] += a1*xv.y;
        y0[2] += a0*xv.z; y1[2] += a1*xv.z;
        y0[3] += a0*xv.w; y1[3] += a1*xv.w;
    }
    // LN + SiLU per pixel, write hidden back into xs
    #pragma unroll
    for (int q = 0; q < 4; q++) {
        float s = y0[q] + y1[q];
        #pragma unroll
        for (int o = 16; o; o >>= 1) s += __shfl_xor_sync(0xffffffffu, s, o);
        float mean = s * (1.f/64.f);
        float d0 = y0[q] - mean, d1 = y1[q] - mean;
        float v = d0*d0 + d1*d1;
        #pragma unroll
        for (int o = 16; o; o >>= 1) v += __shfl_xor_sync(0xffffffffu, v, o);
        float rstd = rsqrtf(v * (1.f/64.f) + 1e-6f);
        float h0 = gs[lane]    * d0 * rstd + bes[lane];
        float h1 = gs[lane+32] * d1 * rstd + bes[lane+32];
        h0 = h0 / (1.f + __expf(-h0));
        h1 = h1 / (1.f + __expf(-h1));
        xs[w][lane][q]      = h0;
        xs[w][lane + 32][q] = h1;
    }
    __syncwarp();

    #pragma unroll
    for (int q = 0; q < 4; q++) { y0[q] = b2s[lane]; y1[q] = b2s[lane+32]; }
    for (int c = 0; c < 64; c++) {
        float a0 = W2s[c*64 + lane], a1 = W2s[c*64 + lane + 32];
        float4 xv = *(const float4*)&xs[w][c][0];
        y0[0] += a0*xv.x; y1[0] += a1*xv.x;
        y0[1] += a0*xv.y; y1[1] += a1*xv.y;
        y0[2] += a0*xv.z; y1[2] += a1*xv.z;
        y0[3] += a0*xv.w; y1[3] += a1*xv.w;
    }
    #pragma unroll
    for (int q = 0; q < 4; q++) {
        int p = pbase + q;
        g_px[p*CC + lane]      = y0[q];
        g_px[p*CC + lane + 32] = y1[q];
    }
}

// ---------------------------------------------------------------------------
// K2: bilateral combined kernel: comb0[n] = exp(-||px_nbr-px||^2/(2C)) * sw[n]
// (0 when neighbor out of bounds). warp-per-pixel.
// ---------------------------------------------------------------------------
__global__ __launch_bounds__(256) void k_bilateral(const float* __restrict__ sigma)
{
    __shared__ float sw_s[N2];
    int tid = threadIdx.x, lane = tid & 31, w = tid >> 5;
    if (tid < N2) {
        float sg = *sigma;
        int dy = tid / 7 - 3, dx = tid % 7 - 3;
        float d2 = (float)(dy*dy + dx*dx);
        sw_s[tid] = __expf(-d2 / (2.f * sg * sg));
    }
    __syncthreads();

    int p = blockIdx.x * 8 + w;
    int b = p / HWP, pp = p % HWP, yy = pp / WW, xx = pp % WW;

    float c0 = g_px[p*CC + lane], c1 = g_px[p*CC + lane + 32];

    for (int n = 0; n < N2; n++) {
        int dy = n / 7 - 3, dx = n % 7 - 3;
        int ny = yy + dy, nx = xx + dx;
        float outv = 0.f;
        if (ny >= 0 && ny < HH && nx >= 0 && nx < WW) {
            const float* q = &g_px[(b*HWP + ny*WW + nx)*CC];
            float d0 = q[lane]    - c0;
            float d1 = q[lane+32] - c1;
            float s = d0*d0 + d1*d1;
            #pragma unroll
            for (int o = 16; o; o >>= 1) s += __shfl_xor_sync(0xffffffffu, s, o);
            outv = __expf(-s * (1.f/128.f)) * sw_s[n];   // 2*C = 128
        }
        if (lane == 0) g_comb[p*N2 + n] = outv;
    }
}

// ---------------------------------------------------------------------------
// K3a: fixup: f = conv49x113 -> LN(49) -> SiLU -> conv49x49; gate + normalize
// warp handles 4 pixels concurrently; x in xs[j][4] -> LDS.128 broadcast.
// Weights zero-padded to 64 output lanes -> branch-free lanes.
// ---------------------------------------------------------------------------
__global__ __launch_bounds__(256) void k_fixup(
    const float* __restrict__ w1, const float* __restrict__ b1,
    const float* __restrict__ g,  const float* __restrict__ be,
    const float* __restrict__ w2, const float* __restrict__ b2)
{
    __shared__ float W1p[113*64];   // [j][o], o padded to 64
    __shared__ float W2p[49*64];
    __shared__ float b1p[64], gp[64], bep[64], b2p[64];
    __shared__ __align__(16) float xs[8][113][4];
    int tid = threadIdx.x, lane = tid & 31, w = tid >> 5;

    for (int i = tid; i < 113*64; i += 256) {
        int j = i >> 6, o = i & 63;
        W1p[i] = (o < 49) ? w1[o*113 + j] : 0.f;
    }
    for (int i = tid; i < 49*64; i += 256) {
        int j = i >> 6, o = i & 63;
        W2p[i] = (o < 49) ? w2[o*49 + j] : 0.f;
    }
    if (tid < 64) {
        b1p[tid] = (tid < 49) ? b1[tid] : 0.f;
        gp[tid]  = (tid < 49) ? g[tid]  : 0.f;
        bep[tid] = (tid < 49) ? be[tid] : 0.f;
        b2p[tid] = (tid < 49) ? b2[tid] : 0.f;
    }

    const bool has2 = (lane + 32) < N2;  // lane < 17
    int pbase = blockIdx.x * 32 + w * 4;

    // stage 4 pixels: comb(49) ++ sem(64) into xs[j][q]
    #pragma unroll
    for (int q = 0; q < 4; q++) {
        int p = pbase + q;
        for (int j = lane; j < 113; j += 32)
            xs[w][j][q] = (j < N2) ? g_comb[p*N2 + j] : g_sem_t[p*CC + (j - N2)];
    }
    __syncthreads();   // weights ready (also covers warp-local xs)

    // keep original combined weights before xs gets overwritten
    float cb0[4], cb1[4];
    #pragma unroll
    for (int q = 0; q < 4; q++) {
        cb0[q] = xs[w][lane][q];
        cb1[q] = has2 ? xs[w][lane + 32][q] : 0.f;
    }

    float y0[4], y1[4];
    #pragma unroll
    for (int q = 0; q < 4; q++) { y0[q] = b1p[lane]; y1[q] = b1p[lane+32]; }

    for (int j = 0; j < 113; j++) {
        float a0 = W1p[j*64 + lane], a1 = W1p[j*64 + lane + 32];
        float4 xv = *(const float4*)&xs[w][j][0];
        y0[0] += a0*xv.x; y1[0] += a1*xv.x;
        y0[1] += a0*xv.y; y1[1] += a1*xv.y;
        y0[2] += a0*xv.z; y1[2] += a1*xv.z;
        y0[3] += a0*xv.w; y1[3] += a1*xv.w;
    }

    // LN(49) + SiLU per pixel, hidden written back into xs[j<49][q]
    #pragma unroll
    for (int q = 0; q < 4; q++) {
        float s = y0[q] + (has2 ? y1[q] : 0.f);
        #pragma unroll
        for (int o = 16; o; o >>= 1) s += __shfl_xor_sync(0xffffffffu, s, o);
        float mean = s * (1.f/49.f);
        float d0 = y0[q] - mean, d1 = y1[q] - mean;
        float v = d0*d0 + (has2 ? d1*d1 : 0.f);
        #pragma unroll
        for (int o = 16; o; o >>= 1) v += __shfl_xor_sync(0xffffffffu, v, o);
        float rstd = rsqrtf(v * (1.f/49.f) + 1e-6f);
        float h0 = gp[lane]      * d0 * rstd + bep[lane];
        float h1 = gp[lane + 32] * d1 * rstd + bep[lane + 32];
        h0 = h0 / (1.f + __expf(-h0));
        h1 = h1 / (1.f + __expf(-h1));
        xs[w][lane][q] = h0;
        if (has2) xs[w][lane + 32][q] = h1;
    }
    __syncwarp();

    #pragma unroll
    for (int q = 0; q < 4; q++) { y0[q] = b2p[lane]; y1[q] = b2p[lane+32]; }
    for (int j = 0; j < 49; j++) {
        float a0 = W2p[j*64 + lane], a1 = W2p[j*64 + lane + 32];
        float4 xv = *(const float4*)&xs[w][j][0];
        y0[0] += a0*xv.x; y1[0] += a1*xv.x;
        y0[1] += a0*xv.y; y1[1] += a1*xv.y;
        y0[2] += a0*xv.z; y1[2] += a1*xv.z;
        y0[3] += a0*xv.w; y1[3] += a1*xv.w;
    }

    #pragma unroll
    for (int q = 0; q < 4; q++) {
        int p = pbase + q;
        float wv0 = cb0[q] * (1.f + 1.f/(1.f + __expf(-y0[q])));
        float wv1 = cb1[q] * (1.f + 1.f/(1.f + __expf(-y1[q])));
        float ss = wv0 + wv1;
        #pragma unroll
        for (int o = 16; o; o >>= 1) ss += __shfl_xor_sync(0xffffffffu, ss, o);
        float inv = 1.f / (ss + 1e-7f);
        g_comb[p*N2 + lane] = wv0 * inv;
        if (has2) g_comb[p*N2 + lane + 32] = wv1 * inv;
    }
}

// ---------------------------------------------------------------------------
// K3b: weighted neighborhood reduction + output_proj (conv -> LN -> conv)
// warp handles 4 pixels: gather per-pixel, convs batched via os[c][4].
// ---------------------------------------------------------------------------
__global__ __launch_bounds__(256) void k_output(
    const float* __restrict__ w1, const float* __restrict__ b1,
    const float* __restrict__ g,  const float* __restrict__ be,
    const float* __restrict__ w2, const float* __restrict__ b2,
    float* __restrict__ out)
{
    __shared__ float W1s[4096], W2s[4096];
    __shared__ float b1s[64], gs[64], bes[64], b2s[64];
    __shared__ float wsb[8][52];
    __shared__ __align__(16) float os[8][64][4];
    int tid = threadIdx.x, lane = tid & 31, w = tid >> 5;

    for (int i = tid; i < 4096; i += 256) {
        int o = i >> 6, c = i & 63;
        W1s[c*64 + o] = w1[i];
        W2s[c*64 + o] = w2[i];
    }
    if (tid < 64) { b1s[tid]=b1[tid]; gs[tid]=g[tid]; bes[tid]=be[tid]; b2s[tid]=b2[tid]; }
    __syncthreads();

    int pbase = blockIdx.x * 32 + w * 4;
    int ppix[4], bidx[4];

    // Gather phase: one pixel at a time, results into os[c][q]
    for (int q = 0; q < 4; q++) {
        int p = pbase + q;
        int b = p / HWP, pp = p % HWP, yy = pp / WW, xx = pp % WW;
        ppix[q] = pp; bidx[q] = b;

        for (int n = lane; n < N2; n += 32) wsb[w][n] = g_comb[p*N2 + n];
        __syncwarp();

        float a0 = 0.f, a1 = 0.f;
        for (int n = 0; n < N2; n++) {
            int dy = n / 7 - 3, dx = n % 7 - 3;
            int ny = yy + dy, nx = xx + dx;
            if (ny >= 0 && ny < HH && nx >= 0 && nx < WW) {
                float wv = wsb[w][n];
                const float* sp = &g_spa_t[(b*HWP + ny*WW + nx)*CC];
                a0 += sp[lane]      * wv;
                a1 += sp[lane + 32] * wv;
            }
        }
        os[w][lane][q]      = a0;
        os[w][lane + 32][q] = a1;
        __syncwarp();
    }

    float y0[4], y1[4];
    #pragma unroll
    for (int q = 0; q < 4; q++) { y0[q] = b1s[lane]; y1[q] = b1s[lane+32]; }
    for (int c = 0; c < 64; c++) {
        float a0 = W1s[c*64 + lane], a1 = W1s[c*64 + lane + 32];
        float4 xv = *(const float4*)&os[w][c][0];
        y0[0] += a0*xv.x; y1[0] += a1*xv.x;
        y0[1] += a0*xv.y; y1[1] += a1*xv.y;
        y0[2] += a0*xv.z; y1[2] += a1*xv.z;
        y0[3] += a0*xv.w; y1[3] += a1*xv.w;
    }

    #pragma unroll
    for (int q = 0; q < 4; q++) {
        float s = y0[q] + y1[q];
        #pragma unroll
        for (int o = 16; o; o >>= 1) s += __shfl_xor_sync(0xffffffffu, s, o);
        float mean = s * (1.f/64.f);
        float d0 = y0[q] - mean, d1 = y1[q] - mean;
        float v = d0*d0 + d1*d1;
        #pragma unroll
        for (int o = 16; o; o >>= 1) v += __shfl_xor_sync(0xffffffffu, v, o);
        float rstd = rsqrtf(v * (1.f/64.f) + 1e-6f);
        float t0 = gs[lane]      * d0 * rstd + bes[lane];
        float t1 = gs[lane + 32] * d1 * rstd + bes[lane + 32];
        os[w][lane][q]      = t0;
        os[w][lane + 32][q] = t1;
    }
    __syncwarp();

    #pragma unroll
    for (int q = 0; q < 4; q++) { y0[q] = b2s[lane]; y1[q] = b2s[lane+32]; }
    for (int c = 0; c < 64; c++) {
        float a0 = W2s[c*64 + lane], a1 = W2s[c*64 + lane + 32];
        float4 xv = *(const float4*)&os[w][c][0];
        y0[0] += a0*xv.x; y1[0] += a1*xv.x;
        y0[1] += a0*xv.y; y1[1] += a1*xv.y;
        y0[2] += a0*xv.z; y1[2] += a1*xv.z;
        y0[3] += a0*xv.w; y1[3] += a1*xv.w;
    }

    #pragma unroll
    for (int q = 0; q < 4; q++) {
        out[(bidx[q]*CC + lane)*HWP + ppix[q]]      = y0[q];
        out[(bidx[q]*CC + lane + 32)*HWP + ppix[q]] = y1[q];
    }
}

// ---------------------------------------------------------------------------
extern "C" void kernel_launch(void* const* d_in, const int* in_sizes, int n_in,
                              void* d_out, int out_size)
{
    const float* spa = (const float*)d_in[0];
    const float* sem = (const float*)d_in[1];

    dim3 tg(HWP/32, CC/32, BB), tb(32, 8);
    k_transpose2<<<tg, tb>>>(sem, spa);

    k_range<<<NPIX/32, 256>>>((const float*)d_in[2], (const float*)d_in[3],
                              (const float*)d_in[4], (const float*)d_in[5],
                              (const float*)d_in[6], (const float*)d_in[7]);

    k_bilateral<<<NPIX/8, 256>>>((const float*)d_in[20]);

    k_fixup<<<NPIX/32, 256>>>((const float*)d_in[8],  (const float*)d_in[9],
                              (const float*)d_in[10], (const float*)d_in[11],
                              (const float*)d_in[12], (const float*)d_in[13]);

    k_output<<<NPIX/32, 256>>>((const float*)d_in[14], (const float*)d_in[15],
                               (const float*)d_in[16], (const float*)d_in[17],
                               (const float*)d_in[18], (const float*)d_in[19],
                               (float*)d_out);
}

// round 5
// speedup vs baseline: 1.4367x; 1.2645x over previous
#include <cuda_runtime.h>

// ---------------------------------------------------------------------------
// SpatialRangeAttention — GB300 sm_103a
// ---------------------------------------------------------------------------

#define BB   2
#define CC   64
#define HH   112
#define WW   112
#define HWP  (HH*WW)      // 12544
#define NPIX (BB*HWP)     // 25088
#define N2   49

// Scratch (pixel-major layouts)
__device__ float g_sem_t[NPIX*CC];   // semantic transposed [pix][c]
__device__ float g_spa_t[NPIX*CC];   // spatial  transposed [pix][c]
__device__ float g_px[NPIX*CC];      // range-projected features [pix][c]
__device__ float g_comb[NPIX*N2];    // bilateral / final weights [pix][n]

// ---------------------------------------------------------------------------
// K0: transpose both inputs [B,C,HW] -> [B*HW, C]
// ---------------------------------------------------------------------------
__global__ __launch_bounds__(256) void k_transpose2(
    const float* __restrict__ sem, const float* __restrict__ spa)
{
    __shared__ float t1[32][33];
    __shared__ float t2[32][33];
    int b  = blockIdx.z;
    int c0 = blockIdx.y * 32;
    int p0 = blockIdx.x * 32;
    int tx = threadIdx.x, ty = threadIdx.y;
    #pragma unroll
    for (int i = ty; i < 32; i += 8) {
        int c = c0 + i, p = p0 + tx;
        t1[i][tx] = sem[(b*CC + c)*HWP + p];
        t2[i][tx] = spa[(b*CC + c)*HWP + p];
    }
    __syncthreads();
    #pragma unroll
    for (int i = ty; i < 32; i += 8) {
        int p = p0 + i, c = c0 + tx;
        g_sem_t[(b*HWP + p)*CC + c] = t1[tx][i];
        g_spa_t[(b*HWP + p)*CC + c] = t2[tx][i];
    }
}

// ---------------------------------------------------------------------------
// K1: range_proj: px = conv1x1(W2) . silu(LN(conv1x1(W1) . sem))
// ---------------------------------------------------------------------------
__global__ __launch_bounds__(256, 4) void k_range(
    const float* __restrict__ w1, const float* __restrict__ b1,
    const float* __restrict__ g,  const float* __restrict__ be,
    const float* __restrict__ w2, const float* __restrict__ b2)
{
    __shared__ float W1s[4096], W2s[4096];
    __shared__ float b1s[64], gs[64], bes[64], b2s[64];
    __shared__ __align__(16) float xs[8][64][4];
    int tid = threadIdx.x, lane = tid & 31, w = tid >> 5;

    for (int i = tid; i < 4096; i += 256) {
        int o = i >> 6, c = i & 63;
        W1s[c*64 + o] = w1[i];
        W2s[c*64 + o] = w2[i];
    }
    if (tid < 64) { b1s[tid]=b1[tid]; gs[tid]=g[tid]; bes[tid]=be[tid]; b2s[tid]=b2[tid]; }

    int pbase = blockIdx.x * 32 + w * 4;
    #pragma unroll
    for (int q = 0; q < 4; q++) {
        xs[w][lane][q]      = g_sem_t[(pbase+q)*CC + lane];
        xs[w][lane + 32][q] = g_sem_t[(pbase+q)*CC + lane + 32];
    }
    __syncthreads();

    float y0[4], y1[4];
    #pragma unroll
    for (int q = 0; q < 4; q++) { y0[q] = b1s[lane]; y1[q] = b1s[lane+32]; }

    for (int c = 0; c < 64; c++) {
        float a0 = W1s[c*64 + lane], a1 = W1s[c*64 + lane + 32];
        float4 xv = *(const float4*)&xs[w][c][0];
        y0[0] += a0*xv.x; y1[0] += a1*xv.x;
        y0[1] += a0*xv.y; y1[1] += a1*xv.y;
        y0[2] += a0*xv.z; y1[2] += a1*xv.z;
        y0[3] += a0*xv.w; y1[3] += a1*xv.w;
    }
    #pragma unroll
    for (int q = 0; q < 4; q++) {
        float s = y0[q] + y1[q];
        #pragma unroll
        for (int o = 16; o; o >>= 1) s += __shfl_xor_sync(0xffffffffu, s, o);
        float mean = s * (1.f/64.f);
        float d0 = y0[q] - mean, d1 = y1[q] - mean;
        float v = d0*d0 + d1*d1;
        #pragma unroll
        for (int o = 16; o; o >>= 1) v += __shfl_xor_sync(0xffffffffu, v, o);
        float rstd = rsqrtf(v * (1.f/64.f) + 1e-6f);
        float h0 = gs[lane]    * d0 * rstd + bes[lane];
        float h1 = gs[lane+32] * d1 * rstd + bes[lane+32];
        h0 = h0 / (1.f + __expf(-h0));
        h1 = h1 / (1.f + __expf(-h1));
        xs[w][lane][q]      = h0;
        xs[w][lane + 32][q] = h1;
    }
    __syncwarp();

    #pragma unroll
    for (int q = 0; q < 4; q++) { y0[q] = b2s[lane]; y1[q] = b2s[lane+32]; }
    for (int c = 0; c < 64; c++) {
        float a0 = W2s[c*64 + lane], a1 = W2s[c*64 + lane + 32];
        float4 xv = *(const float4*)&xs[w][c][0];
        y0[0] += a0*xv.x; y1[0] += a1*xv.x;
        y0[1] += a0*xv.y; y1[1] += a1*xv.y;
        y0[2] += a0*xv.z; y1[2] += a1*xv.z;
        y0[3] += a0*xv.w; y1[3] += a1*xv.w;
    }
    #pragma unroll
    for (int q = 0; q < 4; q++) {
        int p = pbase + q;
        g_px[p*CC + lane]      = y0[q];
        g_px[p*CC + lane + 32] = y1[q];
    }
}

// ---------------------------------------------------------------------------
// K2: bilateral: comb[n] = exp(-||px_nbr-px||^2/(2C)) * sw[n], 0 out of bounds
// warp-per-pixel; dy/dx structured loops, float2 channel loads.
// ---------------------------------------------------------------------------
__global__ __launch_bounds__(256) void k_bilateral(const float* __restrict__ sigma)
{
    __shared__ float sw_s[N2];
    int tid = threadIdx.x, lane = tid & 31, w = tid >> 5;
    if (tid < N2) {
        float sg = *sigma;
        int dy = tid / 7 - 3, dx = tid % 7 - 3;
        float d2 = (float)(dy*dy + dx*dx);
        sw_s[tid] = __expf(-d2 / (2.f * sg * sg));
    }
    __syncthreads();

    int p = blockIdx.x * 8 + w;
    int b = p / HWP, pp = p % HWP, yy = pp / WW, xx = pp % WW;

    float2 cv = *(const float2*)&g_px[p*CC + lane*2];
    float* outp = &g_comb[p*N2];

    int n = 0;
    #pragma unroll
    for (int dy = -3; dy <= 3; dy++) {
        int ny = yy + dy;
        bool rowok = ((unsigned)ny < HH);
        const float* rbase = &g_px[(b*HWP + ny*WW + xx)*CC + lane*2];
        #pragma unroll
        for (int dx = -3; dx <= 3; dx++, n++) {
            int nx = xx + dx;
            float outv = 0.f;
            if (rowok & ((unsigned)nx < WW)) {
                float2 qv = *(const float2*)(rbase + dx*CC);
                float d0 = qv.x - cv.x, d1 = qv.y - cv.y;
                float s = d0*d0 + d1*d1;
                #pragma unroll
                for (int o = 16; o; o >>= 1) s += __shfl_xor_sync(0xffffffffu, s, o);
                outv = __expf(-s * (1.f/128.f)) * sw_s[n];   // 2*C = 128
            }
            if (lane == 0) outp[n] = outv;
        }
    }
}

// ---------------------------------------------------------------------------
// K3a: fixup: conv49x113 -> LN(49) -> SiLU -> conv49x49; gate + normalize.
// Unpadded stride-49 weights (smem 47KB -> 4 blocks/SM); predicated 2nd half.
// ---------------------------------------------------------------------------
__global__ __launch_bounds__(256, 4) void k_fixup(
    const float* __restrict__ w1, const float* __restrict__ b1,
    const float* __restrict__ g,  const float* __restrict__ be,
    const float* __restrict__ w2, const float* __restrict__ b2)
{
    __shared__ float W1u[113*49];   // [j][o], o stride 49
    __shared__ float W2u[49*49];
    __shared__ float b1p[64], gp[64], bep[64], b2p[64];
    __shared__ __align__(16) float xs[8][113][4];
    int tid = threadIdx.x, lane = tid & 31, w = tid >> 5;

    for (int i = tid; i < 113*49; i += 256) {
        int j = i / 49, o = i % 49;
        W1u[i] = w1[o*113 + j];
    }
    for (int i = tid; i < 49*49; i += 256) {
        int j = i / 49, o = i % 49;
        W2u[i] = w2[o*49 + j];
    }
    if (tid < 64) {
        b1p[tid] = (tid < 49) ? b1[tid] : 0.f;
        gp[tid]  = (tid < 49) ? g[tid]  : 0.f;
        bep[tid] = (tid < 49) ? be[tid] : 0.f;
        b2p[tid] = (tid < 49) ? b2[tid] : 0.f;
    }

    const bool has2 = (lane + 32) < N2;  // lane < 17
    int pbase = blockIdx.x * 32 + w * 4;

    #pragma unroll
    for (int q = 0; q < 4; q++) {
        int p = pbase + q;
        for (int j = lane; j < 113; j += 32)
            xs[w][j][q] = (j < N2) ? g_comb[p*N2 + j] : g_sem_t[p*CC + (j - N2)];
    }
    __syncthreads();

    float cb0[4], cb1[4];
    #pragma unroll
    for (int q = 0; q < 4; q++) {
        cb0[q] = xs[w][lane][q];
        cb1[q] = has2 ? xs[w][lane + 32][q] : 0.f;
    }

    float y0[4], y1[4];
    #pragma unroll
    for (int q = 0; q < 4; q++) { y0[q] = b1p[lane]; y1[q] = b1p[lane+32]; }

    for (int j = 0; j < 113; j++) {
        float a0 = W1u[j*49 + lane];
        float a1 = has2 ? W1u[j*49 + lane + 32] : 0.f;
        float4 xv = *(const float4*)&xs[w][j][0];
        y0[0] += a0*xv.x; y1[0] += a1*xv.x;
        y0[1] += a0*xv.y; y1[1] += a1*xv.y;
        y0[2] += a0*xv.z; y1[2] += a1*xv.z;
        y0[3] += a0*xv.w; y1[3] += a1*xv.w;
    }

    #pragma unroll
    for (int q = 0; q < 4; q++) {
        float s = y0[q] + (has2 ? y1[q] : 0.f);
        #pragma unroll
        for (int o = 16; o; o >>= 1) s += __shfl_xor_sync(0xffffffffu, s, o);
        float mean = s * (1.f/49.f);
        float d0 = y0[q] - mean, d1 = y1[q] - mean;
        float v = d0*d0 + (has2 ? d1*d1 : 0.f);
        #pragma unroll
        for (int o = 16; o; o >>= 1) v += __shfl_xor_sync(0xffffffffu, v, o);
        float rstd = rsqrtf(v * (1.f/49.f) + 1e-6f);
        float h0 = gp[lane]      * d0 * rstd + bep[lane];
        float h1 = gp[lane + 32] * d1 * rstd + bep[lane + 32];
        h0 = h0 / (1.f + __expf(-h0));
        h1 = h1 / (1.f + __expf(-h1));
        xs[w][lane][q] = h0;
        if (has2) xs[w][lane + 32][q] = h1;
    }
    __syncwarp();

    #pragma unroll
    for (int q = 0; q < 4; q++) { y0[q] = b2p[lane]; y1[q] = b2p[lane+32]; }
    for (int j = 0; j < 49; j++) {
        float a0 = W2u[j*49 + lane];
        float a1 = has2 ? W2u[j*49 + lane + 32] : 0.f;
        float4 xv = *(const float4*)&xs[w][j][0];
        y0[0] += a0*xv.x; y1[0] += a1*xv.x;
        y0[1] += a0*xv.y; y1[1] += a1*xv.y;
        y0[2] += a0*xv.z; y1[2] += a1*xv.z;
        y0[3] += a0*xv.w; y1[3] += a1*xv.w;
    }

    #pragma unroll
    for (int q = 0; q < 4; q++) {
        int p = pbase + q;
        float wv0 = cb0[q] * (1.f + 1.f/(1.f + __expf(-y0[q])));
        float wv1 = cb1[q] * (1.f + 1.f/(1.f + __expf(-y1[q])));
        float ss = wv0 + wv1;
        #pragma unroll
        for (int o = 16; o; o >>= 1) ss += __shfl_xor_sync(0xffffffffu, ss, o);
        float inv = 1.f / (ss + 1e-7f);
        g_comb[p*N2 + lane] = wv0 * inv;
        if (has2) g_comb[p*N2 + lane + 32] = wv1 * inv;
    }
}

// ---------------------------------------------------------------------------
// K3b: weighted neighborhood reduction + output_proj (conv -> LN -> conv)
// gather uses dy/dx loops + row base pointers + float2 loads.
// ---------------------------------------------------------------------------
__global__ __launch_bounds__(256, 4) void k_output(
    const float* __restrict__ w1, const float* __restrict__ b1,
    const float* __restrict__ g,  const float* __restrict__ be,
    const float* __restrict__ w2, const float* __restrict__ b2,
    float* __restrict__ out)
{
    __shared__ float W1s[4096], W2s[4096];
    __shared__ float b1s[64], gs[64], bes[64], b2s[64];
    __shared__ float wsb[8][52];
    __shared__ __align__(16) float os[8][64][4];
    int tid = threadIdx.x, lane = tid & 31, w = tid >> 5;

    for (int i = tid; i < 4096; i += 256) {
        int o = i >> 6, c = i & 63;
        W1s[c*64 + o] = w1[i];
        W2s[c*64 + o] = w2[i];
    }
    if (tid < 64) { b1s[tid]=b1[tid]; gs[tid]=g[tid]; bes[tid]=be[tid]; b2s[tid]=b2[tid]; }
    __syncthreads();

    int pbase = blockIdx.x * 32 + w * 4;
    int ppix[4], bidx[4];

    // Gather phase: lane owns channels 2*lane, 2*lane+1 (float2)
    for (int q = 0; q < 4; q++) {
        int p = pbase + q;
        int b = p / HWP, pp = p % HWP, yy = pp / WW, xx = pp % WW;
        ppix[q] = pp; bidx[q] = b;

        for (int n = lane; n < N2; n += 32) wsb[w][n] = g_comb[p*N2 + n];
        __syncwarp();

        float a0 = 0.f, a1 = 0.f;
        const float* wrow = &wsb[w][0];
        int n = 0;
        #pragma unroll
        for (int dy = -3; dy <= 3; dy++) {
            int ny = yy + dy;
            bool rowok = ((unsigned)ny < HH);
            const float* rbase = &g_spa_t[(b*HWP + ny*WW + xx)*CC + lane*2];
            #pragma unroll
            for (int dx = -3; dx <= 3; dx++, n++) {
                int nx = xx + dx;
                if (rowok & ((unsigned)nx < WW)) {
                    float wv = wrow[n];
                    float2 sv = *(const float2*)(rbase + dx*CC);
                    a0 += sv.x * wv;
                    a1 += sv.y * wv;
                }
            }
        }
        os[w][lane*2][q]     = a0;
        os[w][lane*2 + 1][q] = a1;
        __syncwarp();
    }

    float y0[4], y1[4];
    #pragma unroll
    for (int q = 0; q < 4; q++) { y0[q] = b1s[lane]; y1[q] = b1s[lane+32]; }
    for (int c = 0; c < 64; c++) {
        float a0 = W1s[c*64 + lane], a1 = W1s[c*64 + lane + 32];
        float4 xv = *(const float4*)&os[w][c][0];
        y0[0] += a0*xv.x; y1[0] += a1*xv.x;
        y0[1] += a0*xv.y; y1[1] += a1*xv.y;
        y0[2] += a0*xv.z; y1[2] += a1*xv.z;
        y0[3] += a0*xv.w; y1[3] += a1*xv.w;
    }

    #pragma unroll
    for (int q = 0; q < 4; q++) {
        float s = y0[q] + y1[q];
        #pragma unroll
        for (int o = 16; o; o >>= 1) s += __shfl_xor_sync(0xffffffffu, s, o);
        float mean = s * (1.f/64.f);
        float d0 = y0[q] - mean, d1 = y1[q] - mean;
        float v = d0*d0 + d1*d1;
        #pragma unroll
        for (int o = 16; o; o >>= 1) v += __shfl_xor_sync(0xffffffffu, v, o);
        float rstd = rsqrtf(v * (1.f/64.f) + 1e-6f);
        float t0 = gs[lane]      * d0 * rstd + bes[lane];
        float t1 = gs[lane + 32] * d1 * rstd + bes[lane + 32];
        os[w][lane][q]      = t0;
        os[w][lane + 32][q] = t1;
    }
    __syncwarp();

    #pragma unroll
    for (int q = 0; q < 4; q++) { y0[q] = b2s[lane]; y1[q] = b2s[lane+32]; }
    for (int c = 0; c < 64; c++) {
        float a0 = W2s[c*64 + lane], a1 = W2s[c*64 + lane + 32];
        float4 xv = *(const float4*)&os[w][c][0];
        y0[0] += a0*xv.x; y1[0] += a1*xv.x;
        y0[1] += a0*xv.y; y1[1] += a1*xv.y;
        y0[2] += a0*xv.z; y1[2] += a1*xv.z;
        y0[3] += a0*xv.w; y1[3] += a1*xv.w;
    }

    #pragma unroll
    for (int q = 0; q < 4; q++) {
        out[(bidx[q]*CC + lane)*HWP + ppix[q]]      = y0[q];
        out[(bidx[q]*CC + lane + 32)*HWP + ppix[q]] = y1[q];
    }
}

// ---------------------------------------------------------------------------
extern "C" void kernel_launch(void* const* d_in, const int* in_sizes, int n_in,
                              void* d_out, int out_size)
{
    const float* spa = (const float*)d_in[0];
    const float* sem = (const float*)d_in[1];

    dim3 tg(HWP/32, CC/32, BB), tb(32, 8);
    k_transpose2<<<tg, tb>>>(sem, spa);

    k_range<<<NPIX/32, 256>>>((const float*)d_in[2], (const float*)d_in[3],
                              (const float*)d_in[4], (const float*)d_in[5],
                              (const float*)d_in[6], (const float*)d_in[7]);

    k_bilateral<<<NPIX/8, 256>>>((const float*)d_in[20]);

    k_fixup<<<NPIX/32, 256>>>((const float*)d_in[8],  (const float*)d_in[9],
                              (const float*)d_in[10], (const float*)d_in[11],
                              (const float*)d_in[12], (const float*)d_in[13]);

    k_output<<<NPIX/32, 256>>>((const float*)d_in[14], (const float*)d_in[15],
                               (const float*)d_in[16], (const float*)d_in[17],
                               (const float*)d_in[18], (const float*)d_in[19],
                               (float*)d_out);
}

// round 6
// speedup vs baseline: 1.6701x; 1.1624x over previous
#include <cuda_runtime.h>

// ---------------------------------------------------------------------------
// SpatialRangeAttention — GB300 sm_103a
// ---------------------------------------------------------------------------

#define BB   2
#define CC   64
#define HH   112
#define WW   112
#define HWP  (HH*WW)      // 12544
#define NPIX (BB*HWP)     // 25088
#define N2   49

// Scratch (pixel-major layouts)
__device__ float g_sem_t[NPIX*CC];   // semantic transposed [pix][c]
__device__ float g_spa_t[NPIX*CC];   // spatial  transposed [pix][c]
__device__ float g_px[NPIX*CC];      // range-projected features [pix][c]
__device__ float g_comb[NPIX*N2];    // bilateral / final weights [pix][n]

// 16-FMA block: weight pair a=(w[o],w[o+32]) times 8 pixel x-values
#define ACC16(a, xa, xb)                              \
    y0[0]+=a.x*xa.x; y1[0]+=a.y*xa.x;                 \
    y0[1]+=a.x*xa.y; y1[1]+=a.y*xa.y;                 \
    y0[2]+=a.x*xa.z; y1[2]+=a.y*xa.z;                 \
    y0[3]+=a.x*xa.w; y1[3]+=a.y*xa.w;                 \
    y0[4]+=a.x*xb.x; y1[4]+=a.y*xb.x;                 \
    y0[5]+=a.x*xb.y; y1[5]+=a.y*xb.y;                 \
    y0[6]+=a.x*xb.z; y1[6]+=a.y*xb.z;                 \
    y0[7]+=a.x*xb.w; y1[7]+=a.y*xb.w;

// ---------------------------------------------------------------------------
// K0: transpose both inputs [B,C,HW] -> [B*HW, C]
// ---------------------------------------------------------------------------
__global__ __launch_bounds__(256) void k_transpose2(
    const float* __restrict__ sem, const float* __restrict__ spa)
{
    __shared__ float t1[32][33];
    __shared__ float t2[32][33];
    int b  = blockIdx.z;
    int c0 = blockIdx.y * 32;
    int p0 = blockIdx.x * 32;
    int tx = threadIdx.x, ty = threadIdx.y;
    #pragma unroll
    for (int i = ty; i < 32; i += 8) {
        int c = c0 + i, p = p0 + tx;
        t1[i][tx] = sem[(b*CC + c)*HWP + p];
        t2[i][tx] = spa[(b*CC + c)*HWP + p];
    }
    __syncthreads();
    #pragma unroll
    for (int i = ty; i < 32; i += 8) {
        int p = p0 + i, c = c0 + tx;
        g_sem_t[(b*HWP + p)*CC + c] = t1[tx][i];
        g_spa_t[(b*HWP + p)*CC + c] = t2[tx][i];
    }
}

// ---------------------------------------------------------------------------
// K1: range_proj: px = conv1x1(W2) . silu(LN(conv1x1(W1) . sem))
// warp = 8 pixels; float2-interleaved weights; dynamic smem 50176B.
// ---------------------------------------------------------------------------
__global__ __launch_bounds__(256, 3) void k_range(
    const float* __restrict__ w1, const float* __restrict__ b1,
    const float* __restrict__ g,  const float* __restrict__ be,
    const float* __restrict__ w2, const float* __restrict__ b2)
{
    extern __shared__ float sm[];
    float2* W1v = (float2*)sm;              // [64][32] f2
    float2* W2v = (float2*)(sm + 4096);     // [64][32] f2
    float*  b1s = sm + 8192;
    float*  gs  = sm + 8256;
    float*  bes = sm + 8320;
    float*  b2s = sm + 8384;
    float*  xs  = sm + 8448;                // [8 warps][64][8]
    int tid = threadIdx.x, lane = tid & 31, w = tid >> 5;

    for (int i = tid; i < 2048; i += 256) {
        int c = i >> 5, l = i & 31;
        W1v[i] = make_float2(w1[l*64 + c], w1[(l+32)*64 + c]);
        W2v[i] = make_float2(w2[l*64 + c], w2[(l+32)*64 + c]);
    }
    if (tid < 64) { b1s[tid]=b1[tid]; gs[tid]=g[tid]; bes[tid]=be[tid]; b2s[tid]=b2[tid]; }

    int pbase = blockIdx.x * 64 + w * 8;
    float* xw = xs + w * 512;

    // stage 8 pixels, register-buffered -> float4 smem stores
    {
        float v0[8], v1[8];
        #pragma unroll
        for (int q = 0; q < 8; q++) {
            v0[q] = g_sem_t[(pbase+q)*CC + lane];
            v1[q] = g_sem_t[(pbase+q)*CC + lane + 32];
        }
        *(float4*)&xw[lane*8]          = make_float4(v0[0],v0[1],v0[2],v0[3]);
        *(float4*)&xw[lane*8 + 4]      = make_float4(v0[4],v0[5],v0[6],v0[7]);
        *(float4*)&xw[(lane+32)*8]     = make_float4(v1[0],v1[1],v1[2],v1[3]);
        *(float4*)&xw[(lane+32)*8 + 4] = make_float4(v1[4],v1[5],v1[6],v1[7]);
    }
    __syncthreads();

    float y0[8], y1[8];
    #pragma unroll
    for (int q = 0; q < 8; q++) { y0[q] = b1s[lane]; y1[q] = b1s[lane+32]; }

    for (int c = 0; c < 64; c++) {
        float2 a = W1v[c*32 + lane];
        float4 xa = *(const float4*)(xw + c*8);
        float4 xb = *(const float4*)(xw + c*8 + 4);
        ACC16(a, xa, xb)
    }

    // LN + SiLU (single-pass mean/var), register-buffered writeback
    {
        float h0[8], h1[8];
        #pragma unroll
        for (int q = 0; q < 8; q++) {
            float s = y0[q] + y1[q];
            float t = y0[q]*y0[q] + y1[q]*y1[q];
            #pragma unroll
            for (int o = 16; o; o >>= 1) {
                s += __shfl_xor_sync(0xffffffffu, s, o);
                t += __shfl_xor_sync(0xffffffffu, t, o);
            }
            float mean = s * (1.f/64.f);
            float var  = t * (1.f/64.f) - mean*mean;
            float rstd = rsqrtf(var + 1e-6f);
            float a0 = gs[lane]    * (y0[q]-mean) * rstd + bes[lane];
            float a1 = gs[lane+32] * (y1[q]-mean) * rstd + bes[lane+32];
            h0[q] = a0 / (1.f + __expf(-a0));
            h1[q] = a1 / (1.f + __expf(-a1));
        }
        __syncwarp();
        *(float4*)&xw[lane*8]          = make_float4(h0[0],h0[1],h0[2],h0[3]);
        *(float4*)&xw[lane*8 + 4]      = make_float4(h0[4],h0[5],h0[6],h0[7]);
        *(float4*)&xw[(lane+32)*8]     = make_float4(h1[0],h1[1],h1[2],h1[3]);
        *(float4*)&xw[(lane+32)*8 + 4] = make_float4(h1[4],h1[5],h1[6],h1[7]);
        __syncwarp();
    }

    #pragma unroll
    for (int q = 0; q < 8; q++) { y0[q] = b2s[lane]; y1[q] = b2s[lane+32]; }
    for (int c = 0; c < 64; c++) {
        float2 a = W2v[c*32 + lane];
        float4 xa = *(const float4*)(xw + c*8);
        float4 xb = *(const float4*)(xw + c*8 + 4);
        ACC16(a, xa, xb)
    }
    #pragma unroll
    for (int q = 0; q < 8; q++) {
        int p = pbase + q;
        g_px[p*CC + lane]      = y0[q];
        g_px[p*CC + lane + 32] = y1[q];
    }
}

// ---------------------------------------------------------------------------
// K2: bilateral: comb[n] = exp(-||px_nbr-px||^2/(2C)) * sw[n], 0 out of bounds
// warp-per-pixel; register-staged results -> 2 coalesced stores.
// ---------------------------------------------------------------------------
__global__ __launch_bounds__(256) void k_bilateral(const float* __restrict__ sigma)
{
    __shared__ float sw_s[N2];
    int tid = threadIdx.x, lane = tid & 31, w = tid >> 5;
    if (tid < N2) {
        float sg = *sigma;
        int dy = tid / 7 - 3, dx = tid % 7 - 3;
        float d2 = (float)(dy*dy + dx*dx);
        sw_s[tid] = __expf(-d2 / (2.f * sg * sg));
    }
    __syncthreads();

    int p = blockIdx.x * 8 + w;
    int b = p / HWP, pp = p % HWP, yy = pp / WW, xx = pp % WW;

    float2 cv = *(const float2*)&g_px[p*CC + lane*2];
    float* outp = &g_comb[p*N2];

    float r0 = 0.f, r1 = 0.f;
    int n = 0;
    #pragma unroll
    for (int dy = -3; dy <= 3; dy++) {
        int ny = yy + dy;
        bool rowok = ((unsigned)ny < HH);
        const float* rbase = &g_px[(b*HWP + ny*WW + xx)*CC + lane*2];
        #pragma unroll
        for (int dx = -3; dx <= 3; dx++, n++) {
            int nx = xx + dx;
            float outv = 0.f;
            if (rowok & ((unsigned)nx < WW)) {
                float2 qv = *(const float2*)(rbase + dx*CC);
                float d0 = qv.x - cv.x, d1 = qv.y - cv.y;
                float s = d0*d0 + d1*d1;
                #pragma unroll
                for (int o = 16; o; o >>= 1) s += __shfl_xor_sync(0xffffffffu, s, o);
                outv = __expf(-s * (1.f/128.f)) * sw_s[n];   // 2*C = 128
            }
            if (n < 32) { if (lane == n)      r0 = outv; }
            else        { if (lane == n - 32) r1 = outv; }
        }
    }
    outp[lane] = r0;
    if (lane < N2 - 32) outp[32 + lane] = r1;
}

// ---------------------------------------------------------------------------
// K3a: fixup: conv49x113 -> LN(49) -> SiLU -> conv49x49; gate + normalize.
// warp = 8 pixels; padded float2 weights; dynamic smem 71424B (3 blk/SM,
// grid 392 = single wave).
// ---------------------------------------------------------------------------
__global__ __launch_bounds__(256, 3) void k_fixup(
    const float* __restrict__ w1, const float* __restrict__ b1,
    const float* __restrict__ g,  const float* __restrict__ be,
    const float* __restrict__ w2, const float* __restrict__ b2)
{
    extern __shared__ float sm[];
    float2* W1v = (float2*)sm;               // [113][32] f2
    float2* W2v = (float2*)(sm + 7232);      // [49][32] f2
    float*  b1p = sm + 10368;
    float*  gp  = sm + 10432;
    float*  bep = sm + 10496;
    float*  b2p = sm + 10560;
    float*  xs  = sm + 10624;                // [8 warps][113][8]
    int tid = threadIdx.x, lane = tid & 31, w = tid >> 5;

    for (int i = tid; i < 113*32; i += 256) {
        int j = i >> 5, l = i & 31;
        float a = (l < N2)      ? w1[l*113 + j]      : 0.f;
        float c = (l+32 < N2)   ? w1[(l+32)*113 + j] : 0.f;
        W1v[i] = make_float2(a, c);
    }
    for (int i = tid; i < 49*32; i += 256) {
        int j = i >> 5, l = i & 31;
        float a = (l < N2)    ? w2[l*49 + j]      : 0.f;
        float c = (l+32 < N2) ? w2[(l+32)*49 + j] : 0.f;
        W2v[i] = make_float2(a, c);
    }
    if (tid < 64) {
        b1p[tid] = (tid < N2) ? b1[tid] : 0.f;
        gp[tid]  = (tid < N2) ? g[tid]  : 0.f;
        bep[tid] = (tid < N2) ? be[tid] : 0.f;
        b2p[tid] = (tid < N2) ? b2[tid] : 0.f;
    }

    const bool has2 = (lane + 32) < N2;  // lane < 17
    int pbase = blockIdx.x * 64 + w * 8;
    float* xw = xs + w * 904;

    #pragma unroll
    for (int q = 0; q < 8; q++) {
        int p = pbase + q;
        for (int j = lane; j < 113; j += 32)
            xw[j*8 + q] = (j < N2) ? g_comb[p*N2 + j] : g_sem_t[p*CC + (j - N2)];
    }
    __syncthreads();

    float y0[8], y1[8];
    #pragma unroll
    for (int q = 0; q < 8; q++) { y0[q] = b1p[lane]; y1[q] = b1p[lane+32]; }

    for (int j = 0; j < 113; j++) {
        float2 a = W1v[j*32 + lane];
        float4 xa = *(const float4*)(xw + j*8);
        float4 xb = *(const float4*)(xw + j*8 + 4);
        ACC16(a, xa, xb)
    }

    // LN(49) + SiLU, register-buffered writeback
    {
        float h0[8], h1[8];
        #pragma unroll
        for (int q = 0; q < 8; q++) {
            float s = y0[q] + (has2 ? y1[q] : 0.f);
            float t = y0[q]*y0[q] + (has2 ? y1[q]*y1[q] : 0.f);
            #pragma unroll
            for (int o = 16; o; o >>= 1) {
                s += __shfl_xor_sync(0xffffffffu, s, o);
                t += __shfl_xor_sync(0xffffffffu, t, o);
            }
            float mean = s * (1.f/49.f);
            float var  = t * (1.f/49.f) - mean*mean;
            float rstd = rsqrtf(var + 1e-6f);
            float a0 = gp[lane]    * (y0[q]-mean) * rstd + bep[lane];
            float a1 = gp[lane+32] * (y1[q]-mean) * rstd + bep[lane+32];
            h0[q] = a0 / (1.f + __expf(-a0));
            h1[q] = a1 / (1.f + __expf(-a1));
        }
        __syncwarp();
        *(float4*)&xw[lane*8]     = make_float4(h0[0],h0[1],h0[2],h0[3]);
        *(float4*)&xw[lane*8 + 4] = make_float4(h0[4],h0[5],h0[6],h0[7]);
        if (has2) {
            *(float4*)&xw[(lane+32)*8]     = make_float4(h1[0],h1[1],h1[2],h1[3]);
            *(float4*)&xw[(lane+32)*8 + 4] = make_float4(h1[4],h1[5],h1[6],h1[7]);
        }
        __syncwarp();
    }

    #pragma unroll
    for (int q = 0; q < 8; q++) { y0[q] = b2p[lane]; y1[q] = b2p[lane+32]; }
    for (int j = 0; j < 49; j++) {
        float2 a = W2v[j*32 + lane];
        float4 xa = *(const float4*)(xw + j*8);
        float4 xb = *(const float4*)(xw + j*8 + 4);
        ACC16(a, xa, xb)
    }

    #pragma unroll
    for (int q = 0; q < 8; q++) {
        int p = pbase + q;
        float cb0 = g_comb[p*N2 + lane];
        float cb1 = has2 ? g_comb[p*N2 + lane + 32] : 0.f;
        float wv0 = cb0 * (1.f + 1.f/(1.f + __expf(-y0[q])));
        float wv1 = cb1 * (1.f + 1.f/(1.f + __expf(-y1[q])));
        float ss = wv0 + wv1;
        #pragma unroll
        for (int o = 16; o; o >>= 1) ss += __shfl_xor_sync(0xffffffffu, ss, o);
        float inv = 1.f / (ss + 1e-7f);
        g_comb[p*N2 + lane] = wv0 * inv;
        if (has2) g_comb[p*N2 + lane + 32] = wv1 * inv;
    }
}

// ---------------------------------------------------------------------------
// K3b: weighted neighborhood reduction + output_proj (conv -> LN -> conv)
// warp = 8 pixels; gather accumulated in regs -> float4 smem stores.
// ---------------------------------------------------------------------------
__global__ __launch_bounds__(256, 3) void k_output(
    const float* __restrict__ w1, const float* __restrict__ b1,
    const float* __restrict__ g,  const float* __restrict__ be,
    const float* __restrict__ w2, const float* __restrict__ b2,
    float* __restrict__ out)
{
    extern __shared__ float sm[];
    float2* W1v = (float2*)sm;              // [64][32] f2
    float2* W2v = (float2*)(sm + 4096);
    float*  b1s = sm + 8192;
    float*  gs  = sm + 8256;
    float*  bes = sm + 8320;
    float*  b2s = sm + 8384;
    float*  wsb = sm + 8448;                // [8][52]
    float*  os  = sm + 8864;                // [8][64][8]
    int tid = threadIdx.x, lane = tid & 31, w = tid >> 5;

    for (int i = tid; i < 2048; i += 256) {
        int c = i >> 5, l = i & 31;
        W1v[i] = make_float2(w1[l*64 + c], w1[(l+32)*64 + c]);
        W2v[i] = make_float2(w2[l*64 + c], w2[(l+32)*64 + c]);
    }
    if (tid < 64) { b1s[tid]=b1[tid]; gs[tid]=g[tid]; bes[tid]=be[tid]; b2s[tid]=b2[tid]; }
    __syncthreads();

    int pbase = blockIdx.x * 64 + w * 8;
    float* ow   = os  + w * 512;
    float* wrow = wsb + w * 52;

    // Gather: lane owns channels (2*lane, 2*lane+1); a[q] in registers
    {
        float a0[8], a1[8];
        for (int q = 0; q < 8; q++) {
            int p = pbase + q;
            int b = p / HWP, pp = p % HWP, yy = pp / WW, xx = pp % WW;

            for (int n = lane; n < N2; n += 32) wrow[n] = g_comb[p*N2 + n];
            __syncwarp();

            float s0 = 0.f, s1 = 0.f;
            int n = 0;
            #pragma unroll
            for (int dy = -3; dy <= 3; dy++) {
                int ny = yy + dy;
                bool rowok = ((unsigned)ny < HH);
                const float* rbase = &g_spa_t[(b*HWP + ny*WW + xx)*CC + lane*2];
                #pragma unroll
                for (int dx = -3; dx <= 3; dx++, n++) {
                    int nx = xx + dx;
                    if (rowok & ((unsigned)nx < WW)) {
                        float wv = wrow[n];
                        float2 sv = *(const float2*)(rbase + dx*CC);
                        s0 += sv.x * wv;
                        s1 += sv.y * wv;
                    }
                }
            }
            a0[q] = s0; a1[q] = s1;
            __syncwarp();
        }
        *(float4*)&ow[(lane*2)*8]       = make_float4(a0[0],a0[1],a0[2],a0[3]);
        *(float4*)&ow[(lane*2)*8 + 4]   = make_float4(a0[4],a0[5],a0[6],a0[7]);
        *(float4*)&ow[(lane*2+1)*8]     = make_float4(a1[0],a1[1],a1[2],a1[3]);
        *(float4*)&ow[(lane*2+1)*8 + 4] = make_float4(a1[4],a1[5],a1[6],a1[7]);
        __syncwarp();
    }

    float y0[8], y1[8];
    #pragma unroll
    for (int q = 0; q < 8; q++) { y0[q] = b1s[lane]; y1[q] = b1s[lane+32]; }
    for (int c = 0; c < 64; c++) {
        float2 a = W1v[c*32 + lane];
        float4 xa = *(const float4*)(ow + c*8);
        float4 xb = *(const float4*)(ow + c*8 + 4);
        ACC16(a, xa, xb)
    }

    {
        float h0[8], h1[8];
        #pragma unroll
        for (int q = 0; q < 8; q++) {
            float s = y0[q] + y1[q];
            float t = y0[q]*y0[q] + y1[q]*y1[q];
            #pragma unroll
            for (int o = 16; o; o >>= 1) {
                s += __shfl_xor_sync(0xffffffffu, s, o);
                t += __shfl_xor_sync(0xffffffffu, t, o);
            }
            float mean = s * (1.f/64.f);
            float var  = t * (1.f/64.f) - mean*mean;
            float rstd = rsqrtf(var + 1e-6f);
            h0[q] = gs[lane]    * (y0[q]-mean) * rstd + bes[lane];
            h1[q] = gs[lane+32] * (y1[q]-mean) * rstd + bes[lane+32];
        }
        __syncwarp();
        *(float4*)&ow[lane*8]          = make_float4(h0[0],h0[1],h0[2],h0[3]);
        *(float4*)&ow[lane*8 + 4]      = make_float4(h0[4],h0[5],h0[6],h0[7]);
        *(float4*)&ow[(lane+32)*8]     = make_float4(h1[0],h1[1],h1[2],h1[3]);
        *(float4*)&ow[(lane+32)*8 + 4] = make_float4(h1[4],h1[5],h1[6],h1[7]);
        __syncwarp();
    }

    #pragma unroll
    for (int q = 0; q < 8; q++) { y0[q] = b2s[lane]; y1[q] = b2s[lane+32]; }
    for (int c = 0; c < 64; c++) {
        float2 a = W2v[c*32 + lane];
        float4 xa = *(const float4*)(ow + c*8);
        float4 xb = *(const float4*)(ow + c*8 + 4);
        ACC16(a, xa, xb)
    }

    #pragma unroll
    for (int q = 0; q < 8; q++) {
        int p = pbase + q;
        int b = p / HWP, pp = p % HWP;
        out[(b*CC + lane)*HWP + pp]      = y0[q];
        out[(b*CC + lane + 32)*HWP + pp] = y1[q];
    }
}

// ---------------------------------------------------------------------------
extern "C" void kernel_launch(void* const* d_in, const int* in_sizes, int n_in,
                              void* d_out, int out_size)
{
    const float* spa = (const float*)d_in[0];
    const float* sem = (const float*)d_in[1];

    static bool attr_set = false;
    if (!attr_set) {
        cudaFuncSetAttribute(k_range,  cudaFuncAttributeMaxDynamicSharedMemorySize, 50176);
        cudaFuncSetAttribute(k_fixup,  cudaFuncAttributeMaxDynamicSharedMemorySize, 71424);
        cudaFuncSetAttribute(k_output, cudaFuncAttributeMaxDynamicSharedMemorySize, 51840);
        attr_set = true;
    }

    dim3 tg(HWP/32, CC/32, BB), tb(32, 8);
    k_transpose2<<<tg, tb>>>(sem, spa);

    k_range<<<NPIX/64, 256, 50176>>>((const float*)d_in[2], (const float*)d_in[3],
                                     (const float*)d_in[4], (const float*)d_in[5],
                                     (const float*)d_in[6], (const float*)d_in[7]);

    k_bilateral<<<NPIX/8, 256>>>((const float*)d_in[20]);

    k_fixup<<<NPIX/64, 256, 71424>>>((const float*)d_in[8],  (const float*)d_in[9],
                                     (const float*)d_in[10], (const float*)d_in[11],
                                     (const float*)d_in[12], (const float*)d_in[13]);

    k_output<<<NPIX/64, 256, 51840>>>((const float*)d_in[14], (const float*)d_in[15],
                                      (const float*)d_in[16], (const float*)d_in[17],
                                      (const float*)d_in[18], (const float*)d_in[19],
                                      (float*)d_out);
}

// round 7
// speedup vs baseline: 1.8932x; 1.1336x over previous
#include <cuda_runtime.h>

// ---------------------------------------------------------------------------
// SpatialRangeAttention — GB300 sm_103a
// ---------------------------------------------------------------------------

#define BB   2
#define CC   64
#define HH   112
#define WW   112
#define HWP  (HH*WW)      // 12544
#define NPIX (BB*HWP)     // 25088
#define N2   49

// Scratch
__device__ float g_sem_t[NPIX*CC];   // semantic transposed [pix][c]
__device__ float g_spa_t[NPIX*CC];   // spatial  transposed [pix][c]
__device__ float g_px_cm[NPIX*CC];   // range-projected, CHANNEL-major [b][c][hw]
__device__ float g_nrm[NPIX];        // per-pixel ||px||^2
__device__ float g_comb[NPIX*N2];    // bilateral / final weights [pix][n]

// 16-FMA block: weight pair a=(w[o],w[o+32]) times 8 pixel x-values
#define ACC16(a, xa, xb)                              \
    y0[0]+=a.x*xa.x; y1[0]+=a.y*xa.x;                 \
    y0[1]+=a.x*xa.y; y1[1]+=a.y*xa.y;                 \
    y0[2]+=a.x*xa.z; y1[2]+=a.y*xa.z;                 \
    y0[3]+=a.x*xa.w; y1[3]+=a.y*xa.w;                 \
    y0[4]+=a.x*xb.x; y1[4]+=a.y*xb.x;                 \
    y0[5]+=a.x*xb.y; y1[5]+=a.y*xb.y;                 \
    y0[6]+=a.x*xb.z; y1[6]+=a.y*xb.z;                 \
    y0[7]+=a.x*xb.w; y1[7]+=a.y*xb.w;

// ---------------------------------------------------------------------------
// K0: transpose both inputs [B,C,HW] -> [B*HW, C]
// ---------------------------------------------------------------------------
__global__ __launch_bounds__(256) void k_transpose2(
    const float* __restrict__ sem, const float* __restrict__ spa)
{
    __shared__ float t1[32][33];
    __shared__ float t2[32][33];
    int b  = blockIdx.z;
    int c0 = blockIdx.y * 32;
    int p0 = blockIdx.x * 32;
    int tx = threadIdx.x, ty = threadIdx.y;
    #pragma unroll
    for (int i = ty; i < 32; i += 8) {
        int c = c0 + i, p = p0 + tx;
        t1[i][tx] = sem[(b*CC + c)*HWP + p];
        t2[i][tx] = spa[(b*CC + c)*HWP + p];
    }
    __syncthreads();
    #pragma unroll
    for (int i = ty; i < 32; i += 8) {
        int p = p0 + i, c = c0 + tx;
        g_sem_t[(b*HWP + p)*CC + c] = t1[tx][i];
        g_spa_t[(b*HWP + p)*CC + c] = t2[tx][i];
    }
}

// ---------------------------------------------------------------------------
// K1: range_proj: conv -> LN -> SiLU -> conv. Outputs channel-major px + norms.
// ---------------------------------------------------------------------------
__global__ __launch_bounds__(256, 3) void k_range(
    const float* __restrict__ w1, const float* __restrict__ b1,
    const float* __restrict__ g,  const float* __restrict__ be,
    const float* __restrict__ w2, const float* __restrict__ b2)
{
    extern __shared__ float sm[];
    float2* W1v = (float2*)sm;              // [64][32] f2
    float2* W2v = (float2*)(sm + 4096);     // [64][32] f2
    float*  b1s = sm + 8192;
    float*  gs  = sm + 8256;
    float*  bes = sm + 8320;
    float*  b2s = sm + 8384;
    float*  xs  = sm + 8448;                // [8 warps][64][8]
    int tid = threadIdx.x, lane = tid & 31, w = tid >> 5;

    for (int i = tid; i < 2048; i += 256) {
        int c = i >> 5, l = i & 31;
        W1v[i] = make_float2(w1[l*64 + c], w1[(l+32)*64 + c]);
        W2v[i] = make_float2(w2[l*64 + c], w2[(l+32)*64 + c]);
    }
    if (tid < 64) { b1s[tid]=b1[tid]; gs[tid]=g[tid]; bes[tid]=be[tid]; b2s[tid]=b2[tid]; }

    int pbase = blockIdx.x * 64 + w * 8;
    float* xw = xs + w * 512;

    {
        float v0[8], v1[8];
        #pragma unroll
        for (int q = 0; q < 8; q++) {
            v0[q] = g_sem_t[(pbase+q)*CC + lane];
            v1[q] = g_sem_t[(pbase+q)*CC + lane + 32];
        }
        *(float4*)&xw[lane*8]          = make_float4(v0[0],v0[1],v0[2],v0[3]);
        *(float4*)&xw[lane*8 + 4]      = make_float4(v0[4],v0[5],v0[6],v0[7]);
        *(float4*)&xw[(lane+32)*8]     = make_float4(v1[0],v1[1],v1[2],v1[3]);
        *(float4*)&xw[(lane+32)*8 + 4] = make_float4(v1[4],v1[5],v1[6],v1[7]);
    }
    __syncthreads();

    float y0[8], y1[8];
    #pragma unroll
    for (int q = 0; q < 8; q++) { y0[q] = b1s[lane]; y1[q] = b1s[lane+32]; }

    #pragma unroll 4
    for (int c = 0; c < 64; c++) {
        float2 a = W1v[c*32 + lane];
        float4 xa = *(const float4*)(xw + c*8);
        float4 xb = *(const float4*)(xw + c*8 + 4);
        ACC16(a, xa, xb)
    }

    {
        float h0[8], h1[8];
        #pragma unroll
        for (int q = 0; q < 8; q++) {
            float s = y0[q] + y1[q];
            float t = y0[q]*y0[q] + y1[q]*y1[q];
            #pragma unroll
            for (int o = 16; o; o >>= 1) {
                s += __shfl_xor_sync(0xffffffffu, s, o);
                t += __shfl_xor_sync(0xffffffffu, t, o);
            }
            float mean = s * (1.f/64.f);
            float var  = t * (1.f/64.f) - mean*mean;
            float rstd = rsqrtf(var + 1e-6f);
            float a0 = gs[lane]    * (y0[q]-mean) * rstd + bes[lane];
            float a1 = gs[lane+32] * (y1[q]-mean) * rstd + bes[lane+32];
            h0[q] = a0 / (1.f + __expf(-a0));
            h1[q] = a1 / (1.f + __expf(-a1));
        }
        __syncwarp();
        *(float4*)&xw[lane*8]          = make_float4(h0[0],h0[1],h0[2],h0[3]);
        *(float4*)&xw[lane*8 + 4]      = make_float4(h0[4],h0[5],h0[6],h0[7]);
        *(float4*)&xw[(lane+32)*8]     = make_float4(h1[0],h1[1],h1[2],h1[3]);
        *(float4*)&xw[(lane+32)*8 + 4] = make_float4(h1[4],h1[5],h1[6],h1[7]);
        __syncwarp();
    }

    #pragma unroll
    for (int q = 0; q < 8; q++) { y0[q] = b2s[lane]; y1[q] = b2s[lane+32]; }
    #pragma unroll 4
    for (int c = 0; c < 64; c++) {
        float2 a = W2v[c*32 + lane];
        float4 xa = *(const float4*)(xw + c*8);
        float4 xb = *(const float4*)(xw + c*8 + 4);
        ACC16(a, xa, xb)
    }

    // norms per pixel
    #pragma unroll
    for (int q = 0; q < 8; q++) {
        float t = y0[q]*y0[q] + y1[q]*y1[q];
        #pragma unroll
        for (int o = 16; o; o >>= 1) t += __shfl_xor_sync(0xffffffffu, t, o);
        if (lane == 0) g_nrm[pbase + q] = t;
    }
    // channel-major stores (8 consecutive pixels per lane -> 2x STG.128)
    {
        int b = pbase / HWP, pp = pbase % HWP;
        float* d0 = &g_px_cm[(size_t)(b*CC + lane)*HWP + pp];
        *(float4*)d0       = make_float4(y0[0],y0[1],y0[2],y0[3]);
        *(float4*)(d0 + 4) = make_float4(y0[4],y0[5],y0[6],y0[7]);
        float* d1 = &g_px_cm[(size_t)(b*CC + lane + 32)*HWP + pp];
        *(float4*)d1       = make_float4(y1[0],y1[1],y1[2],y1[3]);
        *(float4*)(d1 + 4) = make_float4(y1[4],y1[5],y1[6],y1[7]);
    }
}

// ---------------------------------------------------------------------------
// K2: bilateral via dot-form: dist2 = |n|^2+|c|^2-2dot. Warp = (32 pixels, dy).
// Lane = pixel; coalesced channel-major loads; 7 dx accumulators; no shuffles.
// ---------------------------------------------------------------------------
__global__ __launch_bounds__(256) void k_bilateral(const float* __restrict__ sigma)
{
    int wid  = (blockIdx.x << 3) + (threadIdx.x >> 5);
    int lane = threadIdx.x & 31;
    int gpix = wid / 7;
    int dyi  = wid - gpix*7;
    int dy   = dyi - 3;

    int p  = (gpix << 5) + lane;
    int b  = p / HWP, pp = p % HWP, yy = pp / WW, xx = pp % WW;
    int ny = yy + dy;
    bool rowok = ((unsigned)ny < HH);
    int nrow = (rowok ? ny : yy) * WW;

    const float* base = g_px_cm + (size_t)b * (CC*HWP);

    int off[7]; unsigned okm = 0;
    #pragma unroll
    for (int i = 0; i < 7; i++) {
        int nx = xx + i - 3;
        bool o = rowok & ((unsigned)nx < WW);
        okm |= (o ? 1u : 0u) << i;
        off[i] = nrow + (o ? nx : xx);
    }

    float acc[7] = {0.f,0.f,0.f,0.f,0.f,0.f,0.f};
    #pragma unroll 4
    for (int c = 0; c < CC; c++) {
        const float* rc = base + c*HWP;
        float cv = rc[pp];
        #pragma unroll
        for (int i = 0; i < 7; i++) acc[i] += cv * rc[off[i]];
    }

    float nc = g_nrm[p];
    float sg = *sigma;
    float is2 = 0.5f / (sg*sg);
    float* outp = &g_comb[p*N2 + dyi*7];
    const float* nrmb = &g_nrm[b*HWP];
    #pragma unroll
    for (int i = 0; i < 7; i++) {
        float res = 0.f;
        if ((okm >> i) & 1u) {
            float d2 = fmaxf(nrmb[off[i]] + nc - 2.f*acc[i], 0.f);
            float fdx = (float)(i - 3);
            res = __expf(-d2*(1.f/128.f) - ((float)(dy*dy) + fdx*fdx)*is2);
        }
        outp[i] = res;
    }
}

// ---------------------------------------------------------------------------
// K3a: fixup: conv49x113 -> LN(49) -> SiLU -> conv49x49; gate + normalize.
// ---------------------------------------------------------------------------
__global__ __launch_bounds__(256, 3) void k_fixup(
    const float* __restrict__ w1, const float* __restrict__ b1,
    const float* __restrict__ g,  const float* __restrict__ be,
    const float* __restrict__ w2, const float* __restrict__ b2)
{
    extern __shared__ float sm[];
    float2* W1v = (float2*)sm;               // [113][32] f2
    float2* W2v = (float2*)(sm + 7232);      // [49][32] f2
    float*  b1p = sm + 10368;
    float*  gp  = sm + 10432;
    float*  bep = sm + 10496;
    float*  b2p = sm + 10560;
    float*  xs  = sm + 10624;                // [8 warps][113][8]
    int tid = threadIdx.x, lane = tid & 31, w = tid >> 5;

    for (int i = tid; i < 113*32; i += 256) {
        int j = i >> 5, l = i & 31;
        float a = (l < N2)      ? w1[l*113 + j]      : 0.f;
        float c = (l+32 < N2)   ? w1[(l+32)*113 + j] : 0.f;
        W1v[i] = make_float2(a, c);
    }
    for (int i = tid; i < 49*32; i += 256) {
        int j = i >> 5, l = i & 31;
        float a = (l < N2)    ? w2[l*49 + j]      : 0.f;
        float c = (l+32 < N2) ? w2[(l+32)*49 + j] : 0.f;
        W2v[i] = make_float2(a, c);
    }
    if (tid < 64) {
        b1p[tid] = (tid < N2) ? b1[tid] : 0.f;
        gp[tid]  = (tid < N2) ? g[tid]  : 0.f;
        bep[tid] = (tid < N2) ? be[tid] : 0.f;
        b2p[tid] = (tid < N2) ? b2[tid] : 0.f;
    }

    const bool has2 = (lane + 32) < N2;  // lane < 17
    int pbase = blockIdx.x * 64 + w * 8;
    float* xw = xs + w * 904;

    #pragma unroll
    for (int q = 0; q < 8; q++) {
        int p = pbase + q;
        for (int j = lane; j < 113; j += 32)
            xw[j*8 + q] = (j < N2) ? g_comb[p*N2 + j] : g_sem_t[p*CC + (j - N2)];
    }
    __syncthreads();

    float y0[8], y1[8];
    #pragma unroll
    for (int q = 0; q < 8; q++) { y0[q] = b1p[lane]; y1[q] = b1p[lane+32]; }

    #pragma unroll 4
    for (int j = 0; j < 113; j++) {
        float2 a = W1v[j*32 + lane];
        float4 xa = *(const float4*)(xw + j*8);
        float4 xb = *(const float4*)(xw + j*8 + 4);
        ACC16(a, xa, xb)
    }

    {
        float h0[8], h1[8];
        #pragma unroll
        for (int q = 0; q < 8; q++) {
            float s = y0[q] + (has2 ? y1[q] : 0.f);
            float t = y0[q]*y0[q] + (has2 ? y1[q]*y1[q] : 0.f);
            #pragma unroll
            for (int o = 16; o; o >>= 1) {
                s += __shfl_xor_sync(0xffffffffu, s, o);
                t += __shfl_xor_sync(0xffffffffu, t, o);
            }
            float mean = s * (1.f/49.f);
            float var  = t * (1.f/49.f) - mean*mean;
            float rstd = rsqrtf(var + 1e-6f);
            float a0 = gp[lane]    * (y0[q]-mean) * rstd + bep[lane];
            float a1 = gp[lane+32] * (y1[q]-mean) * rstd + bep[lane+32];
            h0[q] = a0 / (1.f + __expf(-a0));
            h1[q] = a1 / (1.f + __expf(-a1));
        }
        __syncwarp();
        *(float4*)&xw[lane*8]     = make_float4(h0[0],h0[1],h0[2],h0[3]);
        *(float4*)&xw[lane*8 + 4] = make_float4(h0[4],h0[5],h0[6],h0[7]);
        if (has2) {
            *(float4*)&xw[(lane+32)*8]     = make_float4(h1[0],h1[1],h1[2],h1[3]);
            *(float4*)&xw[(lane+32)*8 + 4] = make_float4(h1[4],h1[5],h1[6],h1[7]);
        }
        __syncwarp();
    }

    #pragma unroll
    for (int q = 0; q < 8; q++) { y0[q] = b2p[lane]; y1[q] = b2p[lane+32]; }
    #pragma unroll 4
    for (int j = 0; j < 49; j++) {
        float2 a = W2v[j*32 + lane];
        float4 xa = *(const float4*)(xw + j*8);
        float4 xb = *(const float4*)(xw + j*8 + 4);
        ACC16(a, xa, xb)
    }

    #pragma unroll
    for (int q = 0; q < 8; q++) {
        int p = pbase + q;
        float cb0 = g_comb[p*N2 + lane];
        float cb1 = has2 ? g_comb[p*N2 + lane + 32] : 0.f;
        float wv0 = cb0 * (1.f + 1.f/(1.f + __expf(-y0[q])));
        float wv1 = cb1 * (1.f + 1.f/(1.f + __expf(-y1[q])));
        float ss = wv0 + wv1;
        #pragma unroll
        for (int o = 16; o; o >>= 1) ss += __shfl_xor_sync(0xffffffffu, ss, o);
        float inv = 1.f / (ss + 1e-7f);
        g_comb[p*N2 + lane] = wv0 * inv;
        if (has2) g_comb[p*N2 + lane + 32] = wv1 * inv;
    }
}

// ---------------------------------------------------------------------------
// K3b: weighted neighborhood reduction + output_proj (conv -> LN -> conv)
// ---------------------------------------------------------------------------
__global__ __launch_bounds__(256, 3) void k_output(
    const float* __restrict__ w1, const float* __restrict__ b1,
    const float* __restrict__ g,  const float* __restrict__ be,
    const float* __restrict__ w2, const float* __restrict__ b2,
    float* __restrict__ out)
{
    extern __shared__ float sm[];
    float2* W1v = (float2*)sm;              // [64][32] f2
    float2* W2v = (float2*)(sm + 4096);
    float*  b1s = sm + 8192;
    float*  gs  = sm + 8256;
    float*  bes = sm + 8320;
    float*  b2s = sm + 8384;
    float*  wsb = sm + 8448;                // [8][52]
    float*  os  = sm + 8864;                // [8][64][8]
    int tid = threadIdx.x, lane = tid & 31, w = tid >> 5;

    for (int i = tid; i < 2048; i += 256) {
        int c = i >> 5, l = i & 31;
        W1v[i] = make_float2(w1[l*64 + c], w1[(l+32)*64 + c]);
        W2v[i] = make_float2(w2[l*64 + c], w2[(l+32)*64 + c]);
    }
    if (tid < 64) { b1s[tid]=b1[tid]; gs[tid]=g[tid]; bes[tid]=be[tid]; b2s[tid]=b2[tid]; }
    __syncthreads();

    int pbase = blockIdx.x * 64 + w * 8;
    float* ow   = os  + w * 512;
    float* wrow = wsb + w * 52;

    {
        float a0[8], a1[8];
        for (int q = 0; q < 8; q++) {
            int p = pbase + q;
            int b = p / HWP, pp = p % HWP, yy = pp / WW, xx = pp % WW;

            for (int n = lane; n < N2; n += 32) wrow[n] = g_comb[p*N2 + n];
            __syncwarp();

            float s0 = 0.f, s1 = 0.f;
            int n = 0;
            #pragma unroll
            for (int dy = -3; dy <= 3; dy++) {
                int ny = yy + dy;
                bool rowok = ((unsigned)ny < HH);
                const float* rbase = &g_spa_t[(b*HWP + ny*WW + xx)*CC + lane*2];
                #pragma unroll
                for (int dx = -3; dx <= 3; dx++, n++) {
                    int nx = xx + dx;
                    if (rowok & ((unsigned)nx < WW)) {
                        float wv = wrow[n];
                        float2 sv = *(const float2*)(rbase + dx*CC);
                        s0 += sv.x * wv;
                        s1 += sv.y * wv;
                    }
                }
            }
            a0[q] = s0; a1[q] = s1;
            __syncwarp();
        }
        *(float4*)&ow[(lane*2)*8]       = make_float4(a0[0],a0[1],a0[2],a0[3]);
        *(float4*)&ow[(lane*2)*8 + 4]   = make_float4(a0[4],a0[5],a0[6],a0[7]);
        *(float4*)&ow[(lane*2+1)*8]     = make_float4(a1[0],a1[1],a1[2],a1[3]);
        *(float4*)&ow[(lane*2+1)*8 + 4] = make_float4(a1[4],a1[5],a1[6],a1[7]);
        __syncwarp();
    }

    float y0[8], y1[8];
    #pragma unroll
    for (int q = 0; q < 8; q++) { y0[q] = b1s[lane]; y1[q] = b1s[lane+32]; }
    #pragma unroll 4
    for (int c = 0; c < 64; c++) {
        float2 a = W1v[c*32 + lane];
        float4 xa = *(const float4*)(ow + c*8);
        float4 xb = *(const float4*)(ow + c*8 + 4);
        ACC16(a, xa, xb)
    }

    {
        float h0[8], h1[8];
        #pragma unroll
        for (int q = 0; q < 8; q++) {
            float s = y0[q] + y1[q];
            float t = y0[q]*y0[q] + y1[q]*y1[q];
            #pragma unroll
            for (int o = 16; o; o >>= 1) {
                s += __shfl_xor_sync(0xffffffffu, s, o);
                t += __shfl_xor_sync(0xffffffffu, t, o);
            }
            float mean = s * (1.f/64.f);
            float var  = t * (1.f/64.f) - mean*mean;
            float rstd = rsqrtf(var + 1e-6f);
            h0[q] = gs[lane]    * (y0[q]-mean) * rstd + bes[lane];
            h1[q] = gs[lane+32] * (y1[q]-mean) * rstd + bes[lane+32];
        }
        __syncwarp();
        *(float4*)&ow[lane*8]          = make_float4(h0[0],h0[1],h0[2],h0[3]);
        *(float4*)&ow[lane*8 + 4]      = make_float4(h0[4],h0[5],h0[6],h0[7]);
        *(float4*)&ow[(lane+32)*8]     = make_float4(h1[0],h1[1],h1[2],h1[3]);
        *(float4*)&ow[(lane+32)*8 + 4] = make_float4(h1[4],h1[5],h1[6],h1[7]);
        __syncwarp();
    }

    #pragma unroll
    for (int q = 0; q < 8; q++) { y0[q] = b2s[lane]; y1[q] = b2s[lane+32]; }
    #pragma unroll 4
    for (int c = 0; c < 64; c++) {
        float2 a = W2v[c*32 + lane];
        float4 xa = *(const float4*)(ow + c*8);
        float4 xb = *(const float4*)(ow + c*8 + 4);
        ACC16(a, xa, xb)
    }

    #pragma unroll
    for (int q = 0; q < 8; q++) {
        int p = pbase + q;
        int b = p / HWP, pp = p % HWP;
        out[(b*CC + lane)*HWP + pp]      = y0[q];
        out[(b*CC + lane + 32)*HWP + pp] = y1[q];
    }
}

// ---------------------------------------------------------------------------
extern "C" void kernel_launch(void* const* d_in, const int* in_sizes, int n_in,
                              void* d_out, int out_size)
{
    const float* spa = (const float*)d_in[0];
    const float* sem = (const float*)d_in[1];

    static bool attr_set = false;
    if (!attr_set) {
        cudaFuncSetAttribute(k_range,  cudaFuncAttributeMaxDynamicSharedMemorySize, 50176);
        cudaFuncSetAttribute(k_fixup,  cudaFuncAttributeMaxDynamicSharedMemorySize, 71424);
        cudaFuncSetAttribute(k_output, cudaFuncAttributeMaxDynamicSharedMemorySize, 51840);
        attr_set = true;
    }

    dim3 tg(HWP/32, CC/32, BB), tb(32, 8);
    k_transpose2<<<tg, tb>>>(sem, spa);

    k_range<<<NPIX/64, 256, 50176>>>((const float*)d_in[2], (const float*)d_in[3],
                                     (const float*)d_in[4], (const float*)d_in[5],
                                     (const float*)d_in[6], (const float*)d_in[7]);

    // warps = (NPIX/32) * 7 = 5488 ; 8 warps/block -> 686 blocks
    k_bilateral<<<686, 256>>>((const float*)d_in[20]);

    k_fixup<<<NPIX/64, 256, 71424>>>((const float*)d_in[8],  (const float*)d_in[9],
                                     (const float*)d_in[10], (const float*)d_in[11],
                                     (const float*)d_in[12], (const float*)d_in[13]);

    k_output<<<NPIX/64, 256, 51840>>>((const float*)d_in[14], (const float*)d_in[15],
                                      (const float*)d_in[16], (const float*)d_in[17],
                                      (const float*)d_in[18], (const float*)d_in[19],
                                      (float*)d_out);
}